// round 7
// baseline (speedup 1.0000x reference)
#include <cuda_runtime.h>
#include <cuda_bf16.h>

#define BS 16
#define NQ 300
#define NT 50
#define KP3 51          // 17 keypoints * 3
#define KPP 52          // padded (float4/ull2-friendly)
#define NCOL (BS*NT)    // 800
#define NROW (BS*NQ)    // 4800
#define NK 10           // columns per lane in LAP (10*32 >= 300)
#define CBLK 160        // cols per cost block
#define RBLK 32         // rows per cost block
#define GBX  (NCOL/CBLK)   // 5
#define GBY  (NROW/RBLK)   // 150
#define THALF 25        // targets per diag pass

// dynamic smem layout (floats)
#define OFF_SDK   (NT*NQ)                 // 15000: sdk[THALF][KPP]
#define OFF_TMN   (OFF_SDK + THALF*KPP)   // +1300
#define OFF_TMX   (OFF_TMN + THALF*3)
#define OFF_TVOL  (OFF_TMX + THALF*3)
#define DYN_FLOATS (OFF_TVOL + THALF)     // 16475
// cost path needs CBLK*(KP3+6) = 9120 floats < DYN_FLOATS

typedef unsigned long long ull;

#define ADD_F32X2(out, a, b) \
    asm("add.rn.f32x2 %0, %1, %2;" : "=l"(out) : "l"(a), "l"(b))

__device__ __forceinline__ unsigned fmap(float f) {
    unsigned u = __float_as_uint(f);
    return (u & 0x80000000u) ? ~u : (u | 0x80000000u);
}
__device__ __forceinline__ float finv(unsigned u) {
    return __uint_as_float((u & 0x80000000u) ? (u & 0x7FFFFFFFu) : ~u);
}
__device__ __forceinline__ int warp_argmin(float& bv, int bi) {
    unsigned bu  = fmap(bv);
    unsigned mvu = __reduce_min_sync(0xffffffffu, bu);
    unsigned bal = __ballot_sync(0xffffffffu, bu == mvu);
    int src = __ffs(bal) - 1;
    bv = finv(mvu);
    return __shfl_sync(0xffffffffu, bi, src);
}

// ---------------------------------------------------------
// Fused kernel. blocks [0,16): diag-cost + LAP.  blocks [16,766): C matrix.
// ---------------------------------------------------------
__global__ void __launch_bounds__(256, 3) fused_kernel(const float* __restrict__ pkp,
                                                       const float* __restrict__ pbox,
                                                       const float* __restrict__ tkp,
                                                       const float* __restrict__ tbox,
                                                       float* __restrict__ out) {
    extern __shared__ __align__(16) float dsm[];
    const int tid = threadIdx.x;

    if (blockIdx.x >= BS) {
        // ================== COST-MATRIX PATH ==================
        float* buf = dsm;
        const int cb = blockIdx.x - BS;
        const int c0 = (cb % GBX) * CBLK;
        const int r0 = (cb / GBX) * RBLK;
        const int c  = c0 + (tid < CBLK ? tid : 0);

        // phase A: target slice -> registers
        for (int i = tid; i < CBLK*KP3; i += 256) buf[i] = tkp[c0*KP3 + i];
        for (int i = tid; i < CBLK*6;  i += 256) buf[CBLK*KP3 + i] = tbox[c0*6 + i];
        __syncthreads();

        ull  ndk[KPP/2];
        float tmn[3], tmx[3], tvol = 0.f;
        {
            float sz[3];
            #pragma unroll
            for (int d = 0; d < 3; d++) {
                float ctr = buf[CBLK*KP3 + (c-c0)*6 + d];
                sz[d]     = buf[CBLK*KP3 + (c-c0)*6 + 3 + d];
                tmn[d] = ctr - 0.5f*sz[d];
                tmx[d] = ctr + 0.5f*sz[d];
            }
            tvol = (tmx[0]-tmn[0])*(tmx[1]-tmn[1])*(tmx[2]-tmn[2]);
            float dk[KPP];
            #pragma unroll
            for (int k = 0; k < KP3; k++) {
                int d = k - (k/3)*3;
                dk[k] = (buf[(c-c0)*KP3 + k] - tmn[d]) / sz[d];
            }
            dk[KP3] = 0.f;
            #pragma unroll
            for (int k2 = 0; k2 < KPP/2; k2++) {
                float lo = -dk[2*k2], hi = -dk[2*k2+1];
                asm("mov.b64 %0, {%1, %2};" : "=l"(ndk[k2]) : "f"(lo), "f"(hi));
            }
        }
        __syncthreads();

        // phase B: pred rows padded to 52 + boxes
        for (int i = tid; i < RBLK*KPP; i += 256) {
            int r = i / KPP, k = i - r*KPP;
            buf[i] = (k < KP3) ? pkp[(size_t)(r0+r)*KP3 + k] : 0.f;
        }
        for (int i = tid; i < RBLK*6; i += 256) buf[RBLK*KPP + i] = pbox[(size_t)r0*6 + i];
        __syncthreads();
        if (tid >= CBLK) return;

        const ull AMASK = 0x7FFFFFFF7FFFFFFFULL;
        #pragma unroll 2
        for (int r = 0; r < RBLK; r++) {
            const ulonglong2* prow = (const ulonglong2*)&buf[r*KPP];
            ull sacc[4] = {0, 0, 0, 0};
            #pragma unroll
            for (int k4 = 0; k4 < KPP/4; k4++) {
                ulonglong2 p = prow[k4];
                ull d0; ADD_F32X2(d0, p.x, ndk[2*k4]);
                d0 &= AMASK;
                ADD_F32X2(sacc[(2*k4)&3], sacc[(2*k4)&3], d0);
                ull d1; ADD_F32X2(d1, p.y, ndk[2*k4+1]);
                d1 &= AMASK;
                ADD_F32X2(sacc[(2*k4+1)&3], sacc[(2*k4+1)&3], d1);
            }
            ull sAB; ADD_F32X2(sAB, sacc[0], sacc[1]);
            ull sCD; ADD_F32X2(sCD, sacc[2], sacc[3]);
            ull st;  ADD_F32X2(st, sAB, sCD);
            float slo, shi;
            asm("mov.b64 {%0, %1}, %2;" : "=f"(slo), "=f"(shi) : "l"(st));
            float s = slo + shi;

            float pmn[3], pmx[3];
            #pragma unroll
            for (int d = 0; d < 3; d++) {
                float cc = buf[RBLK*KPP + r*6 + d];
                float ss = buf[RBLK*KPP + r*6 + 3 + d];
                pmn[d] = cc - 0.5f*ss; pmx[d] = cc + 0.5f*ss;
            }
            float vol1 = (pmx[0]-pmn[0])*(pmx[1]-pmn[1])*(pmx[2]-pmn[2]);
            float inter = 1.f, evol = 1.f;
            #pragma unroll
            for (int d = 0; d < 3; d++) {
                inter *= fmaxf(fminf(pmx[d], tmx[d]) - fmaxf(pmn[d], tmn[d]), 0.f);
                evol  *= fmaxf(fmaxf(pmx[d], tmx[d]) - fminf(pmn[d], tmn[d]), 0.f);
            }
            float uni = vol1 + tvol - inter;
            out[(size_t)(r0+r)*NCOL + c] = s - (inter/uni - (evol - uni)/evol);
        }
        return;
    }

    // ================== LAP PATH (blocks 0..15) ==================
    float* smc   = dsm;                      // [NT*NQ] diag cost block
    float* sdk   = dsm + OFF_SDK;            // [THALF][KPP]
    float* stmn  = dsm + OFF_TMN;            // [THALF][3]
    float* stmx  = dsm + OFF_TMX;
    float* stvol = dsm + OFF_TVOL;
    const int b    = blockIdx.x;
    const int lane = tid & 31;
    const int wid  = tid >> 5;
    const float INF = 3.0e38f;

    __shared__ float u[NT];
    __shared__ float rmin[NT];
    __shared__ int   ramin[NT];
    __shared__ int   path[NQ];
    __shared__ int   row4col[NQ];
    __shared__ int   col4row[NT];
    __shared__ int   selj[NQ + 2];
    __shared__ float selv[NQ + 2];
    __shared__ int   freelist[NT];

    // diag cost block in two passes of 25 targets
    for (int pass = 0; pass < 2; pass++) {
        const int tb = pass * THALF;
        if (tid < THALF) {
            int tt = tb + tid;
            int g = b*NT + tt;
            float sz[3];
            #pragma unroll
            for (int d = 0; d < 3; d++) {
                float ctr = tbox[g*6 + d];
                sz[d]     = tbox[g*6 + 3 + d];
                stmn[tid*3 + d] = ctr - 0.5f*sz[d];
                stmx[tid*3 + d] = ctr + 0.5f*sz[d];
            }
            stvol[tid] = sz[0]*sz[1]*sz[2];
            #pragma unroll
            for (int k = 0; k < KP3; k++) {
                int d = k - (k/3)*3;
                sdk[tid*KPP + k] = (tkp[(size_t)g*KP3 + k] - stmn[tid*3 + d]) / sz[d];
            }
            sdk[tid*KPP + KP3] = 0.f;
        }
        __syncthreads();

        for (int q = tid; q < NQ; q += 256) {
            float4 pk4[KPP/4];
            {
                float tmpk[KPP];
                const float* pr = pkp + (size_t)(b*NQ + q)*KP3;
                #pragma unroll
                for (int k = 0; k < KP3; k++) tmpk[k] = pr[k];
                tmpk[KP3] = 0.f;
                #pragma unroll
                for (int k4 = 0; k4 < KPP/4; k4++)
                    pk4[k4] = make_float4(tmpk[4*k4], tmpk[4*k4+1], tmpk[4*k4+2], tmpk[4*k4+3]);
            }
            float pmn[3], pmx[3];
            #pragma unroll
            for (int d = 0; d < 3; d++) {
                float cc = pbox[(size_t)(b*NQ + q)*6 + d];
                float ss = pbox[(size_t)(b*NQ + q)*6 + 3 + d];
                pmn[d] = cc - 0.5f*ss; pmx[d] = cc + 0.5f*ss;
            }
            float vol1 = (pmx[0]-pmn[0])*(pmx[1]-pmn[1])*(pmx[2]-pmn[2]);

            for (int tr = 0; tr < THALF; tr++) {
                const float4* srow = (const float4*)&sdk[tr*KPP];
                float s0 = 0.f, s1 = 0.f, s2 = 0.f, s3 = 0.f;
                #pragma unroll
                for (int k4 = 0; k4 < KPP/4; k4++) {
                    float4 d4 = srow[k4];
                    s0 += fabsf(pk4[k4].x - d4.x);
                    s1 += fabsf(pk4[k4].y - d4.y);
                    s2 += fabsf(pk4[k4].z - d4.z);
                    s3 += fabsf(pk4[k4].w - d4.w);
                }
                float s = (s0 + s1) + (s2 + s3);
                float inter = 1.f, evol = 1.f;
                #pragma unroll
                for (int d = 0; d < 3; d++) {
                    float tn = stmn[tr*3 + d], tx = stmx[tr*3 + d];
                    inter *= fmaxf(fminf(pmx[d], tx) - fmaxf(pmn[d], tn), 0.f);
                    evol  *= fmaxf(fmaxf(pmx[d], tx) - fminf(pmn[d], tn), 0.f);
                }
                float uni = vol1 + stvol[tr] - inter;
                smc[(tb + tr)*NQ + q] = s - (inter/uni - (evol - uni)/evol);
            }
        }
        __syncthreads();
    }

    // per-row min + argmin (8 warps over 50 rows)
    for (int row = wid; row < NT; row += 8) {
        const float* rp = smc + row*NQ;
        float bv = INF; int bi = NQ;
        for (int j = lane; j < NQ; j += 32) {
            float v = rp[j];
            if (v < bv) { bv = v; bi = j; }
        }
        int fi = warp_argmin(bv, bi);
        if (lane == 0) { rmin[row] = bv; ramin[row] = fi; }
    }
    __syncthreads();
    if (tid >= 32) return;                 // warp 0 solves alone

    float shortest[NK];
    float vloc[NK];

    for (int j = lane; j < NQ; j += 32) row4col[j] = -1;
    for (int t = lane; t < NT; t += 32) { u[t] = rmin[t]; col4row[t] = -1; }
    #pragma unroll
    for (int k = 0; k < NK; k++) vloc[k] = 0.f;
    __syncwarp();

    // greedy conflict-free assignment
    if (lane == 0) {
        #pragma unroll 1
        for (int i = 0; i < NT; i++) {
            int j = ramin[i];
            if (row4col[j] == -1) { row4col[j] = i; col4row[i] = j; }
        }
    }
    __syncwarp();

    // collect unassigned rows
    int nfree = 0;
    #pragma unroll
    for (int base = 0; base < NT; base += 32) {
        int t = base + lane;
        bool fr = (t < NT) && (col4row[t] == -1);
        unsigned m = __ballot_sync(0xffffffffu, fr);
        int pos = nfree + __popc(m & ((1u << lane) - 1u));
        if (fr) freelist[pos] = t;
        nfree += __popc(m);
    }
    __syncwarp();

    // JV augmenting row reduction (displacement chains)
    {
        int scans = 0;
        const int CAP = 8 * NT;
        for (int idx = 0; idx < nfree && scans < CAP; idx++) {
            int i = freelist[idx];
            while (i != -1 && scans < CAP) {
                scans++;
                const float* lrow = smc + i*NQ;
                float l1 = INF, l2 = INF; int b1 = NQ;
                #pragma unroll
                for (int k = 0; k < NK; k++) {
                    int j = k*32 + lane;
                    if (j < NQ) {
                        float w = lrow[j] - vloc[k];
                        if (w < l1) { l2 = l1; l1 = w; b1 = j; }
                        else if (w < l2) l2 = w;
                    }
                }
                unsigned m1 = __reduce_min_sync(0xffffffffu, fmap(l1));
                unsigned bal = __ballot_sync(0xffffffffu, fmap(l1) == m1);
                int win = __ffs(bal) - 1;
                int j1  = __shfl_sync(0xffffffffu, b1, win);
                float u1 = finv(m1);
                float cand = (lane == win) ? l2 : l1;
                float u2 = finv(__reduce_min_sync(0xffffffffu, fmap(cand)));

                int i1 = row4col[j1];
                if (!(u1 < u2) && i1 != -1) break;   // degenerate tie -> Dijkstra
                if (lane == (j1 & 31) && u1 < u2) vloc[j1 >> 5] -= (u2 - u1);
                if (lane == 0) {
                    u[i] = u2;
                    row4col[j1] = i;
                    col4row[i]  = j1;
                    if (i1 != -1) col4row[i1] = -1;
                }
                __syncwarp();
                i = i1;
            }
        }
    }
    __syncwarp();

    // shortest augmenting path for whatever remains
    for (int curRow = 0; curRow < NT; curRow++) {
        if (col4row[curRow] != -1) continue;

        #pragma unroll
        for (int k = 0; k < NK; k++) shortest[k] = INF;
        unsigned sc = 0;
        int   i  = curRow;
        float mv = 0.f;
        int   nsteps = 0;
        int   sink = -1;

        while (true) {
            const float base = mv - u[i];
            const float* lrow = smc + i*NQ;

            float bv = INF; int bi = NQ;
            #pragma unroll
            for (int k = 0; k < NK; k++) {
                int j = k*32 + lane;
                if (j < NQ && !((sc >> k) & 1u)) {
                    float rr = base + lrow[j] - vloc[k];
                    if (rr < shortest[k]) { shortest[k] = rr; path[j] = i; }
                    if (shortest[k] < bv) { bv = shortest[k]; bi = j; }
                }
            }

            int fi = warp_argmin(bv, bi);
            mv = bv;

            if (lane == (fi & 31)) sc |= 1u << (fi >> 5);
            if (lane == 0) { selj[nsteps] = fi; selv[nsteps] = mv; }
            nsteps++;

            int r4 = row4col[fi];
            if (r4 == -1) { sink = fi; break; }
            i = r4;
        }

        __syncwarp();

        if (lane == 0) u[curRow] += mv;
        for (int s = lane; s < nsteps - 1; s += 32) {
            int i2 = row4col[selj[s]];
            u[i2] += mv - selv[s];
        }
        for (int s = 0; s < nsteps; s++) {
            int j = selj[s];
            if ((j & 31) == lane) vloc[j >> 5] -= mv - selv[s];
        }
        __syncwarp();

        if (lane == 0) {
            int j = sink;
            while (true) {
                int i2 = path[j];
                row4col[j] = i2;
                int nj = col4row[i2];
                col4row[i2] = j;
                j = nj;
                if (i2 == curRow) break;
            }
        }
        __syncwarp();
    }

    // emit indices sorted by query (rank counting)
    for (int t = lane; t < NT; t += 32) {
        int q = col4row[t];
        int rank = 0;
        #pragma unroll
        for (int t2 = 0; t2 < NT; t2++) rank += (col4row[t2] < q) ? 1 : 0;
        size_t base = (size_t)NROW * NCOL + (size_t)b * 2 * NT;
        out[base + rank]      = (float)q;
        out[base + NT + rank] = (float)t;
    }
}

// ---------------------------------------------------------
extern "C" void kernel_launch(void* const* d_in, const int* in_sizes, int n_in,
                              void* d_out, int out_size) {
    const float* pred_kp   = (const float*)d_in[0];  // (16,300,51)
    const float* pred_box  = (const float*)d_in[1];  // (16,300,6)
    const float* tgt_box   = (const float*)d_in[2];  // (16,50,6)
    const float* tgt_kp    = (const float*)d_in[3];  // (16,50,51)
    float* out = (float*)d_out;

    const int dyn_smem = DYN_FLOATS * (int)sizeof(float);   // 65900 B
    cudaFuncSetAttribute(fused_kernel, cudaFuncAttributeMaxDynamicSharedMemorySize, dyn_smem);

    fused_kernel<<<BS + GBX*GBY, 256, dyn_smem>>>(pred_kp, pred_box, tgt_kp, tgt_box, out);
}

// round 8
// speedup vs baseline: 1.2819x; 1.2819x over previous
#include <cuda_runtime.h>
#include <cuda_bf16.h>

#define BS 16
#define NQ 300
#define NT 50
#define KP3 51          // 17 keypoints * 3
#define KPP 52          // padded (float4/ull2-friendly)
#define NCOL (BS*NT)    // 800
#define NROW (BS*NQ)    // 4800
#define NK 10           // columns per lane in LAP (10*32 >= 300)
#define CBLK 160        // cols per cost block
#define RBLK 32         // rows per cost block
#define GBX  (NCOL/CBLK)   // 5
#define GBY  (NROW/RBLK)   // 150
#define THALF 25        // targets per diag pass (LAP path)
#define SDS  60         // sd row stride (words): 16B-aligned, conflict-free
#define ACH  80         // phase-A staging chunk (columns)

// dynamic smem layout (floats) -- LAP path
#define OFF_SDK   (NT*NQ)                 // 15000: sdk[THALF][KPP]
#define OFF_TMN   (OFF_SDK + THALF*KPP)
#define OFF_TMX   (OFF_TMN + THALF*3)
#define OFF_TVOL  (OFF_TMX + THALF*3)
#define DYN_FLOATS (OFF_TVOL + THALF)     // 16475
// cost path needs CBLK*SDS + max(ACH*(KP3+6), RBLK*(KPP+6)) = 9600+4560 = 14160 < 16475

typedef unsigned long long ull;

#define ADD_F32X2(out, a, b) \
    asm("add.rn.f32x2 %0, %1, %2;" : "=l"(out) : "l"(a), "l"(b))

__device__ __forceinline__ unsigned fmap(float f) {
    unsigned u = __float_as_uint(f);
    return (u & 0x80000000u) ? ~u : (u | 0x80000000u);
}
__device__ __forceinline__ float finv(unsigned u) {
    return __uint_as_float((u & 0x80000000u) ? (u & 0x7FFFFFFFu) : ~u);
}
__device__ __forceinline__ int warp_argmin(float& bv, int bi) {
    unsigned bu  = fmap(bv);
    unsigned mvu = __reduce_min_sync(0xffffffffu, bu);
    unsigned bal = __ballot_sync(0xffffffffu, bu == mvu);
    int src = __ffs(bal) - 1;
    bv = finv(mvu);
    return __shfl_sync(0xffffffffu, bi, src);
}

// ---------------------------------------------------------
// Fused kernel. blocks [0,16): diag-cost + LAP.  blocks [16,766): C matrix.
// ---------------------------------------------------------
__global__ void __launch_bounds__(256) fused_kernel(const float* __restrict__ pkp,
                                                    const float* __restrict__ pbox,
                                                    const float* __restrict__ tkp,
                                                    const float* __restrict__ tbox,
                                                    float* __restrict__ out) {
    extern __shared__ __align__(16) float dsm[];
    const int tid = threadIdx.x;

    if (blockIdx.x >= BS) {
        // ================== COST-MATRIX PATH ==================
        float* sd    = dsm;               // [CBLK][SDS] negated normalized tgt kp
        float* stage = dsm + CBLK*SDS;    // staging (phase A chunks / phase B pred)
        const int cb = blockIdx.x - BS;
        const int c0 = (cb % GBX) * CBLK;
        const int r0 = (cb / GBX) * RBLK;
        const int cl = (tid < CBLK) ? tid : 0;
        const int c  = c0 + cl;

        float tmn[3], tmx[3], tvol = 0.f;

        // phase A: two chunks of 80 target columns
        #pragma unroll 1
        for (int ch = 0; ch < 2; ch++) {
            const int cc0 = ch * ACH;
            for (int i = tid; i < ACH*KP3; i += 256) stage[i] = tkp[(size_t)(c0+cc0)*KP3 + i];
            for (int i = tid; i < ACH*6;  i += 256) stage[ACH*KP3 + i] = tbox[(size_t)(c0+cc0)*6 + i];
            __syncthreads();
            if (tid >= cc0 && tid < cc0 + ACH) {
                const int lt = tid - cc0;
                float sz[3];
                #pragma unroll
                for (int d = 0; d < 3; d++) {
                    float ctr = stage[ACH*KP3 + lt*6 + d];
                    sz[d]     = stage[ACH*KP3 + lt*6 + 3 + d];
                    tmn[d] = ctr - 0.5f*sz[d];
                    tmx[d] = ctr + 0.5f*sz[d];
                }
                tvol = sz[0]*sz[1]*sz[2];
                #pragma unroll
                for (int k = 0; k < KP3; k++) {
                    int d = k - (k/3)*3;
                    sd[tid*SDS + k] = -((stage[lt*KP3 + k] - tmn[d]) / sz[d]);
                }
                sd[tid*SDS + KP3] = 0.f;   // pad term
            }
            __syncthreads();
        }

        // phase B: pred rows padded to 52 + boxes
        for (int i = tid; i < RBLK*KPP; i += 256) {
            int r = i / KPP, k = i - r*KPP;
            stage[i] = (k < KP3) ? pkp[(size_t)(r0+r)*KP3 + k] : 0.f;
        }
        for (int i = tid; i < RBLK*6; i += 256) stage[RBLK*KPP + i] = pbox[(size_t)r0*6 + i];
        __syncthreads();
        if (tid >= CBLK) return;

        const ull AMASK = 0x7FFFFFFF7FFFFFFFULL;
        const ulonglong2* ndrow = (const ulonglong2*)&sd[tid*SDS];

        #pragma unroll 2
        for (int r = 0; r < RBLK; r++) {
            const ulonglong2* prow = (const ulonglong2*)&stage[r*KPP];
            ull sacc[4] = {0, 0, 0, 0};
            #pragma unroll
            for (int k4 = 0; k4 < KPP/4; k4++) {
                ulonglong2 p  = prow[k4];
                ulonglong2 nd = ndrow[k4];
                ull d0; ADD_F32X2(d0, p.x, nd.x);
                d0 &= AMASK;
                ADD_F32X2(sacc[(2*k4)&3], sacc[(2*k4)&3], d0);
                ull d1; ADD_F32X2(d1, p.y, nd.y);
                d1 &= AMASK;
                ADD_F32X2(sacc[(2*k4+1)&3], sacc[(2*k4+1)&3], d1);
            }
            ull sAB; ADD_F32X2(sAB, sacc[0], sacc[1]);
            ull sCD; ADD_F32X2(sCD, sacc[2], sacc[3]);
            ull st;  ADD_F32X2(st, sAB, sCD);
            float slo, shi;
            asm("mov.b64 {%0, %1}, %2;" : "=f"(slo), "=f"(shi) : "l"(st));
            float s = slo + shi;

            float pmn[3], pmx[3];
            #pragma unroll
            for (int d = 0; d < 3; d++) {
                float cc = stage[RBLK*KPP + r*6 + d];
                float ss = stage[RBLK*KPP + r*6 + 3 + d];
                pmn[d] = cc - 0.5f*ss; pmx[d] = cc + 0.5f*ss;
            }
            float vol1 = (pmx[0]-pmn[0])*(pmx[1]-pmn[1])*(pmx[2]-pmn[2]);
            float inter = 1.f, evol = 1.f;
            #pragma unroll
            for (int d = 0; d < 3; d++) {
                inter *= fmaxf(fminf(pmx[d], tmx[d]) - fmaxf(pmn[d], tmn[d]), 0.f);
                evol  *= fmaxf(fmaxf(pmx[d], tmx[d]) - fminf(pmn[d], tmn[d]), 0.f);
            }
            float uni = vol1 + tvol - inter;
            out[(size_t)(r0+r)*NCOL + c] = s - (inter/uni - (evol - uni)/evol);
        }
        return;
    }

    // ================== LAP PATH (blocks 0..15) ==================
    float* smc   = dsm;                      // [NT*NQ] diag cost block
    float* sdk   = dsm + OFF_SDK;            // [THALF][KPP]
    float* stmn  = dsm + OFF_TMN;            // [THALF][3]
    float* stmx  = dsm + OFF_TMX;
    float* stvol = dsm + OFF_TVOL;
    const int b    = blockIdx.x;
    const int lane = tid & 31;
    const int wid  = tid >> 5;
    const float INF = 3.0e38f;

    __shared__ float u[NT];
    __shared__ float rmin[NT];
    __shared__ int   ramin[NT];
    __shared__ int   path[NQ];
    __shared__ int   row4col[NQ];
    __shared__ int   col4row[NT];
    __shared__ int   selj[NQ + 2];
    __shared__ float selv[NQ + 2];
    __shared__ int   freelist[NT];

    // diag cost block in two passes of 25 targets
    #pragma unroll 1
    for (int pass = 0; pass < 2; pass++) {
        const int tb = pass * THALF;
        if (tid < THALF) {
            int g = b*NT + tb + tid;
            float sz[3];
            #pragma unroll
            for (int d = 0; d < 3; d++) {
                float ctr = tbox[g*6 + d];
                sz[d]     = tbox[g*6 + 3 + d];
                stmn[tid*3 + d] = ctr - 0.5f*sz[d];
                stmx[tid*3 + d] = ctr + 0.5f*sz[d];
            }
            stvol[tid] = sz[0]*sz[1]*sz[2];
            #pragma unroll
            for (int k = 0; k < KP3; k++) {
                int d = k - (k/3)*3;
                sdk[tid*KPP + k] = (tkp[(size_t)g*KP3 + k] - stmn[tid*3 + d]) / sz[d];
            }
            sdk[tid*KPP + KP3] = 0.f;
        }
        __syncthreads();

        for (int q = tid; q < NQ; q += 256) {
            float4 pk4[KPP/4];
            {
                float tmpk[KPP];
                const float* pr = pkp + (size_t)(b*NQ + q)*KP3;
                #pragma unroll
                for (int k = 0; k < KP3; k++) tmpk[k] = pr[k];
                tmpk[KP3] = 0.f;
                #pragma unroll
                for (int k4 = 0; k4 < KPP/4; k4++)
                    pk4[k4] = make_float4(tmpk[4*k4], tmpk[4*k4+1], tmpk[4*k4+2], tmpk[4*k4+3]);
            }
            float pmn[3], pmx[3];
            #pragma unroll
            for (int d = 0; d < 3; d++) {
                float cc = pbox[(size_t)(b*NQ + q)*6 + d];
                float ss = pbox[(size_t)(b*NQ + q)*6 + 3 + d];
                pmn[d] = cc - 0.5f*ss; pmx[d] = cc + 0.5f*ss;
            }
            float vol1 = (pmx[0]-pmn[0])*(pmx[1]-pmn[1])*(pmx[2]-pmn[2]);

            for (int tr = 0; tr < THALF; tr++) {
                const float4* srow = (const float4*)&sdk[tr*KPP];
                float s0 = 0.f, s1 = 0.f, s2 = 0.f, s3 = 0.f;
                #pragma unroll
                for (int k4 = 0; k4 < KPP/4; k4++) {
                    float4 d4 = srow[k4];
                    s0 += fabsf(pk4[k4].x - d4.x);
                    s1 += fabsf(pk4[k4].y - d4.y);
                    s2 += fabsf(pk4[k4].z - d4.z);
                    s3 += fabsf(pk4[k4].w - d4.w);
                }
                float s = (s0 + s1) + (s2 + s3);
                float inter = 1.f, evol = 1.f;
                #pragma unroll
                for (int d = 0; d < 3; d++) {
                    float tn = stmn[tr*3 + d], tx = stmx[tr*3 + d];
                    inter *= fmaxf(fminf(pmx[d], tx) - fmaxf(pmn[d], tn), 0.f);
                    evol  *= fmaxf(fmaxf(pmx[d], tx) - fminf(pmn[d], tn), 0.f);
                }
                float uni = vol1 + stvol[tr] - inter;
                smc[(tb + tr)*NQ + q] = s - (inter/uni - (evol - uni)/evol);
            }
        }
        __syncthreads();
    }

    // per-row min + argmin (8 warps over 50 rows)
    for (int row = wid; row < NT; row += 8) {
        const float* rp = smc + row*NQ;
        float bv = INF; int bi = NQ;
        for (int j = lane; j < NQ; j += 32) {
            float v = rp[j];
            if (v < bv) { bv = v; bi = j; }
        }
        int fi = warp_argmin(bv, bi);
        if (lane == 0) { rmin[row] = bv; ramin[row] = fi; }
    }
    __syncthreads();
    if (tid >= 32) return;                 // warp 0 solves alone

    float shortest[NK];
    float vloc[NK];

    for (int j = lane; j < NQ; j += 32) row4col[j] = -1;
    for (int t = lane; t < NT; t += 32) { u[t] = rmin[t]; col4row[t] = -1; }
    #pragma unroll
    for (int k = 0; k < NK; k++) vloc[k] = 0.f;
    __syncwarp();

    // greedy conflict-free assignment
    if (lane == 0) {
        #pragma unroll 1
        for (int i = 0; i < NT; i++) {
            int j = ramin[i];
            if (row4col[j] == -1) { row4col[j] = i; col4row[i] = j; }
        }
    }
    __syncwarp();

    // collect unassigned rows
    int nfree = 0;
    #pragma unroll
    for (int base = 0; base < NT; base += 32) {
        int t = base + lane;
        bool fr = (t < NT) && (col4row[t] == -1);
        unsigned m = __ballot_sync(0xffffffffu, fr);
        int pos = nfree + __popc(m & ((1u << lane) - 1u));
        if (fr) freelist[pos] = t;
        nfree += __popc(m);
    }
    __syncwarp();

    // JV augmenting row reduction (displacement chains)
    {
        int scans = 0;
        const int CAP = 8 * NT;
        for (int idx = 0; idx < nfree && scans < CAP; idx++) {
            int i = freelist[idx];
            while (i != -1 && scans < CAP) {
                scans++;
                const float* lrow = smc + i*NQ;
                float l1 = INF, l2 = INF; int b1 = NQ;
                #pragma unroll
                for (int k = 0; k < NK; k++) {
                    int j = k*32 + lane;
                    if (j < NQ) {
                        float w = lrow[j] - vloc[k];
                        if (w < l1) { l2 = l1; l1 = w; b1 = j; }
                        else if (w < l2) l2 = w;
                    }
                }
                unsigned m1 = __reduce_min_sync(0xffffffffu, fmap(l1));
                unsigned bal = __ballot_sync(0xffffffffu, fmap(l1) == m1);
                int win = __ffs(bal) - 1;
                int j1  = __shfl_sync(0xffffffffu, b1, win);
                float u1 = finv(m1);
                float cand = (lane == win) ? l2 : l1;
                float u2 = finv(__reduce_min_sync(0xffffffffu, fmap(cand)));

                int i1 = row4col[j1];
                if (!(u1 < u2) && i1 != -1) break;   // degenerate tie -> Dijkstra
                if (lane == (j1 & 31) && u1 < u2) vloc[j1 >> 5] -= (u2 - u1);
                if (lane == 0) {
                    u[i] = u2;
                    row4col[j1] = i;
                    col4row[i]  = j1;
                    if (i1 != -1) col4row[i1] = -1;
                }
                __syncwarp();
                i = i1;
            }
        }
    }
    __syncwarp();

    // shortest augmenting path for whatever remains
    for (int curRow = 0; curRow < NT; curRow++) {
        if (col4row[curRow] != -1) continue;

        #pragma unroll
        for (int k = 0; k < NK; k++) shortest[k] = INF;
        unsigned sc = 0;
        int   i  = curRow;
        float mv = 0.f;
        int   nsteps = 0;
        int   sink = -1;

        while (true) {
            const float base = mv - u[i];
            const float* lrow = smc + i*NQ;

            float bv = INF; int bi = NQ;
            #pragma unroll
            for (int k = 0; k < NK; k++) {
                int j = k*32 + lane;
                if (j < NQ && !((sc >> k) & 1u)) {
                    float rr = base + lrow[j] - vloc[k];
                    if (rr < shortest[k]) { shortest[k] = rr; path[j] = i; }
                    if (shortest[k] < bv) { bv = shortest[k]; bi = j; }
                }
            }

            int fi = warp_argmin(bv, bi);
            mv = bv;

            if (lane == (fi & 31)) sc |= 1u << (fi >> 5);
            if (lane == 0) { selj[nsteps] = fi; selv[nsteps] = mv; }
            nsteps++;

            int r4 = row4col[fi];
            if (r4 == -1) { sink = fi; break; }
            i = r4;
        }

        __syncwarp();

        if (lane == 0) u[curRow] += mv;
        for (int s = lane; s < nsteps - 1; s += 32) {
            int i2 = row4col[selj[s]];
            u[i2] += mv - selv[s];
        }
        for (int s = 0; s < nsteps; s++) {
            int j = selj[s];
            if ((j & 31) == lane) vloc[j >> 5] -= mv - selv[s];
        }
        __syncwarp();

        if (lane == 0) {
            int j = sink;
            while (true) {
                int i2 = path[j];
                row4col[j] = i2;
                int nj = col4row[i2];
                col4row[i2] = j;
                j = nj;
                if (i2 == curRow) break;
            }
        }
        __syncwarp();
    }

    // emit indices sorted by query (rank counting)
    for (int t = lane; t < NT; t += 32) {
        int q = col4row[t];
        int rank = 0;
        #pragma unroll
        for (int t2 = 0; t2 < NT; t2++) rank += (col4row[t2] < q) ? 1 : 0;
        size_t base = (size_t)NROW * NCOL + (size_t)b * 2 * NT;
        out[base + rank]      = (float)q;
        out[base + NT + rank] = (float)t;
    }
}

// ---------------------------------------------------------
extern "C" void kernel_launch(void* const* d_in, const int* in_sizes, int n_in,
                              void* d_out, int out_size) {
    const float* pred_kp   = (const float*)d_in[0];  // (16,300,51)
    const float* pred_box  = (const float*)d_in[1];  // (16,300,6)
    const float* tgt_box   = (const float*)d_in[2];  // (16,50,6)
    const float* tgt_kp    = (const float*)d_in[3];  // (16,50,51)
    float* out = (float*)d_out;

    const int dyn_smem = DYN_FLOATS * (int)sizeof(float);   // 65900 B
    cudaFuncSetAttribute(fused_kernel, cudaFuncAttributeMaxDynamicSharedMemorySize, dyn_smem);

    fused_kernel<<<BS + GBX*GBY, 256, dyn_smem>>>(pred_kp, pred_box, tgt_kp, tgt_box, out);
}

// round 9
// speedup vs baseline: 1.7910x; 1.3972x over previous
#include <cuda_runtime.h>
#include <cuda_bf16.h>

#define BS 16
#define NQ 300
#define NT 50
#define KP3 51          // 17 keypoints * 3
#define KPP 52          // padded (float4/ull2-friendly)
#define NCOL (BS*NT)    // 800
#define NROW (BS*NQ)    // 4800
#define NK 10           // columns per lane in LAP (10*32 >= 300)
#define CBLK 160        // cols per cost block == blockDim
#define TPB  160
#define NWARP (TPB/32)  // 5
#define RBLK 32         // rows per cost block
#define GBX  (NCOL/CBLK)   // 5
#define GBY  (NROW/RBLK)   // 150
#define THALF 25        // targets per diag pass (LAP path)

// dynamic smem layout (floats) -- LAP path
#define OFF_SDK   (NT*NQ)                 // 15000: sdk[THALF][KPP]
#define OFF_TMN   (OFF_SDK + THALF*KPP)
#define OFF_TMX   (OFF_TMN + THALF*3)
#define OFF_TVOL  (OFF_TMX + THALF*3)
#define DYN_FLOATS (OFF_TVOL + THALF)     // 16475
// cost path needs CBLK*(KP3+6) = 9120 floats < 16475

typedef unsigned long long ull;

#define ADD_F32X2(out, a, b) \
    asm("add.rn.f32x2 %0, %1, %2;" : "=l"(out) : "l"(a), "l"(b))

__device__ __forceinline__ float frcp(float x) {
    float r;
    asm("rcp.approx.f32 %0, %1;" : "=f"(r) : "f"(x));
    return r;
}
__device__ __forceinline__ unsigned fmap(float f) {
    unsigned u = __float_as_uint(f);
    return (u & 0x80000000u) ? ~u : (u | 0x80000000u);
}
__device__ __forceinline__ float finv(unsigned u) {
    return __uint_as_float((u & 0x80000000u) ? (u & 0x7FFFFFFFu) : ~u);
}
__device__ __forceinline__ int warp_argmin(float& bv, int bi) {
    unsigned bu  = fmap(bv);
    unsigned mvu = __reduce_min_sync(0xffffffffu, bu);
    unsigned bal = __ballot_sync(0xffffffffu, bu == mvu);
    int src = __ffs(bal) - 1;
    bv = finv(mvu);
    return __shfl_sync(0xffffffffu, bi, src);
}

// ---------------------------------------------------------
// Fused kernel, 160-thread blocks.
// blocks [0,16): diag-cost + LAP.  blocks [16,766): C matrix.
// ---------------------------------------------------------
__global__ void __launch_bounds__(TPB) fused_kernel(const float* __restrict__ pkp,
                                                    const float* __restrict__ pbox,
                                                    const float* __restrict__ tkp,
                                                    const float* __restrict__ tbox,
                                                    float* __restrict__ out) {
    extern __shared__ __align__(16) float dsm[];
    const int tid = threadIdx.x;

    if (blockIdx.x >= BS) {
        // ================== COST-MATRIX PATH ==================
        float* buf = dsm;
        const int cb = blockIdx.x - BS;
        const int c0 = (cb % GBX) * CBLK;
        const int r0 = (cb / GBX) * RBLK;
        const int c  = c0 + tid;            // every thread owns a column

        // phase A: target slice -> registers
        for (int i = tid; i < CBLK*KP3; i += TPB) buf[i] = tkp[(size_t)c0*KP3 + i];
        for (int i = tid; i < CBLK*6;  i += TPB) buf[CBLK*KP3 + i] = tbox[(size_t)c0*6 + i];
        __syncthreads();

        ull  ndk[KPP/2];
        float tmn[3], tmx[3], tvol;
        {
            float sz[3], rsz[3];
            #pragma unroll
            for (int d = 0; d < 3; d++) {
                float ctr = buf[CBLK*KP3 + tid*6 + d];
                sz[d]     = buf[CBLK*KP3 + tid*6 + 3 + d];
                rsz[d]    = frcp(sz[d]);
                tmn[d] = ctr - 0.5f*sz[d];
                tmx[d] = ctr + 0.5f*sz[d];
            }
            tvol = sz[0]*sz[1]*sz[2];
            float dk[KPP];
            #pragma unroll
            for (int k = 0; k < KP3; k++) {
                int d = k - (k/3)*3;
                dk[k] = (buf[tid*KP3 + k] - tmn[d]) * rsz[d];
            }
            dk[KP3] = 0.f;
            #pragma unroll
            for (int k2 = 0; k2 < KPP/2; k2++) {
                float lo = -dk[2*k2], hi = -dk[2*k2+1];
                asm("mov.b64 %0, {%1, %2};" : "=l"(ndk[k2]) : "f"(lo), "f"(hi));
            }
        }
        __syncthreads();

        // phase B: pred rows padded to 52 + boxes
        for (int i = tid; i < RBLK*KPP; i += TPB) {
            int r = i / KPP, k = i - r*KPP;
            buf[i] = (k < KP3) ? pkp[(size_t)(r0+r)*KP3 + k] : 0.f;
        }
        for (int i = tid; i < RBLK*6; i += TPB) buf[RBLK*KPP + i] = pbox[(size_t)r0*6 + i];
        __syncthreads();

        const ull AMASK = 0x7FFFFFFF7FFFFFFFULL;
        #pragma unroll 2
        for (int r = 0; r < RBLK; r++) {
            const ulonglong2* prow = (const ulonglong2*)&buf[r*KPP];
            ull sacc[4] = {0, 0, 0, 0};
            #pragma unroll
            for (int k4 = 0; k4 < KPP/4; k4++) {
                ulonglong2 p = prow[k4];
                ull d0; ADD_F32X2(d0, p.x, ndk[2*k4]);
                d0 &= AMASK;
                ADD_F32X2(sacc[(2*k4)&3], sacc[(2*k4)&3], d0);
                ull d1; ADD_F32X2(d1, p.y, ndk[2*k4+1]);
                d1 &= AMASK;
                ADD_F32X2(sacc[(2*k4+1)&3], sacc[(2*k4+1)&3], d1);
            }
            ull sAB; ADD_F32X2(sAB, sacc[0], sacc[1]);
            ull sCD; ADD_F32X2(sCD, sacc[2], sacc[3]);
            ull st;  ADD_F32X2(st, sAB, sCD);
            float slo, shi;
            asm("mov.b64 {%0, %1}, %2;" : "=f"(slo), "=f"(shi) : "l"(st));
            float s = slo + shi;

            float pmn[3], pmx[3];
            #pragma unroll
            for (int d = 0; d < 3; d++) {
                float cc = buf[RBLK*KPP + r*6 + d];
                float ss = buf[RBLK*KPP + r*6 + 3 + d];
                pmn[d] = cc - 0.5f*ss; pmx[d] = cc + 0.5f*ss;
            }
            float vol1 = (pmx[0]-pmn[0])*(pmx[1]-pmn[1])*(pmx[2]-pmn[2]);
            float inter = 1.f, evol = 1.f;
            #pragma unroll
            for (int d = 0; d < 3; d++) {
                inter *= fmaxf(fminf(pmx[d], tmx[d]) - fmaxf(pmn[d], tmn[d]), 0.f);
                evol  *= fmaxf(fmaxf(pmx[d], tmx[d]) - fminf(pmn[d], tmn[d]), 0.f);
            }
            float uni = vol1 + tvol - inter;
            float giou = inter*frcp(uni) - (evol - uni)*frcp(evol);
            out[(size_t)(r0+r)*NCOL + c] = s - giou;
        }
        return;
    }

    // ================== LAP PATH (blocks 0..15) ==================
    float* smc   = dsm;                      // [NT*NQ] diag cost block
    float* sdk   = dsm + OFF_SDK;            // [THALF][KPP]
    float* stmn  = dsm + OFF_TMN;            // [THALF][3]
    float* stmx  = dsm + OFF_TMX;
    float* stvol = dsm + OFF_TVOL;
    const int b    = blockIdx.x;
    const int lane = tid & 31;
    const int wid  = tid >> 5;
    const float INF = 3.0e38f;

    __shared__ float u[NT];
    __shared__ float rmin[NT];
    __shared__ int   ramin[NT];
    __shared__ int   path[NQ];
    __shared__ int   row4col[NQ];
    __shared__ int   col4row[NT];
    __shared__ int   selj[NQ + 2];
    __shared__ float selv[NQ + 2];
    __shared__ int   freelist[NT];

    // diag cost block in two passes of 25 targets
    #pragma unroll 1
    for (int pass = 0; pass < 2; pass++) {
        const int tb = pass * THALF;
        if (tid < THALF) {
            int g = b*NT + tb + tid;
            float sz[3], rsz[3];
            #pragma unroll
            for (int d = 0; d < 3; d++) {
                float ctr = tbox[g*6 + d];
                sz[d]     = tbox[g*6 + 3 + d];
                rsz[d]    = frcp(sz[d]);
                stmn[tid*3 + d] = ctr - 0.5f*sz[d];
                stmx[tid*3 + d] = ctr + 0.5f*sz[d];
            }
            stvol[tid] = sz[0]*sz[1]*sz[2];
            #pragma unroll
            for (int k = 0; k < KP3; k++) {
                int d = k - (k/3)*3;
                sdk[tid*KPP + k] = (tkp[(size_t)g*KP3 + k] - stmn[tid*3 + d]) * rsz[d];
            }
            sdk[tid*KPP + KP3] = 0.f;
        }
        __syncthreads();

        for (int q = tid; q < NQ; q += TPB) {
            float4 pk4[KPP/4];
            {
                float tmpk[KPP];
                const float* pr = pkp + (size_t)(b*NQ + q)*KP3;
                #pragma unroll
                for (int k = 0; k < KP3; k++) tmpk[k] = pr[k];
                tmpk[KP3] = 0.f;
                #pragma unroll
                for (int k4 = 0; k4 < KPP/4; k4++)
                    pk4[k4] = make_float4(tmpk[4*k4], tmpk[4*k4+1], tmpk[4*k4+2], tmpk[4*k4+3]);
            }
            float pmn[3], pmx[3];
            #pragma unroll
            for (int d = 0; d < 3; d++) {
                float cc = pbox[(size_t)(b*NQ + q)*6 + d];
                float ss = pbox[(size_t)(b*NQ + q)*6 + 3 + d];
                pmn[d] = cc - 0.5f*ss; pmx[d] = cc + 0.5f*ss;
            }
            float vol1 = (pmx[0]-pmn[0])*(pmx[1]-pmn[1])*(pmx[2]-pmn[2]);

            for (int tr = 0; tr < THALF; tr++) {
                const float4* srow = (const float4*)&sdk[tr*KPP];
                float s0 = 0.f, s1 = 0.f, s2 = 0.f, s3 = 0.f;
                #pragma unroll
                for (int k4 = 0; k4 < KPP/4; k4++) {
                    float4 d4 = srow[k4];
                    s0 += fabsf(pk4[k4].x - d4.x);
                    s1 += fabsf(pk4[k4].y - d4.y);
                    s2 += fabsf(pk4[k4].z - d4.z);
                    s3 += fabsf(pk4[k4].w - d4.w);
                }
                float s = (s0 + s1) + (s2 + s3);
                float inter = 1.f, evol = 1.f;
                #pragma unroll
                for (int d = 0; d < 3; d++) {
                    float tn = stmn[tr*3 + d], tx = stmx[tr*3 + d];
                    inter *= fmaxf(fminf(pmx[d], tx) - fmaxf(pmn[d], tn), 0.f);
                    evol  *= fmaxf(fmaxf(pmx[d], tx) - fminf(pmn[d], tn), 0.f);
                }
                float uni = vol1 + stvol[tr] - inter;
                float giou = inter*frcp(uni) - (evol - uni)*frcp(evol);
                smc[(tb + tr)*NQ + q] = s - giou;
            }
        }
        __syncthreads();
    }

    // per-row min + argmin (5 warps over 50 rows)
    for (int row = wid; row < NT; row += NWARP) {
        const float* rp = smc + row*NQ;
        float bv = INF; int bi = NQ;
        for (int j = lane; j < NQ; j += 32) {
            float v = rp[j];
            if (v < bv) { bv = v; bi = j; }
        }
        int fi = warp_argmin(bv, bi);
        if (lane == 0) { rmin[row] = bv; ramin[row] = fi; }
    }
    __syncthreads();
    if (tid >= 32) return;                 // warp 0 solves alone

    float shortest[NK];
    float vloc[NK];

    for (int j = lane; j < NQ; j += 32) row4col[j] = -1;
    for (int t = lane; t < NT; t += 32) { u[t] = rmin[t]; col4row[t] = -1; }
    #pragma unroll
    for (int k = 0; k < NK; k++) vloc[k] = 0.f;
    __syncwarp();

    // greedy conflict-free assignment
    if (lane == 0) {
        #pragma unroll 1
        for (int i = 0; i < NT; i++) {
            int j = ramin[i];
            if (row4col[j] == -1) { row4col[j] = i; col4row[i] = j; }
        }
    }
    __syncwarp();

    // collect unassigned rows
    int nfree = 0;
    #pragma unroll
    for (int base = 0; base < NT; base += 32) {
        int t = base + lane;
        bool fr = (t < NT) && (col4row[t] == -1);
        unsigned m = __ballot_sync(0xffffffffu, fr);
        int pos = nfree + __popc(m & ((1u << lane) - 1u));
        if (fr) freelist[pos] = t;
        nfree += __popc(m);
    }
    __syncwarp();

    // JV augmenting row reduction (displacement chains)
    {
        int scans = 0;
        const int CAP = 8 * NT;
        for (int idx = 0; idx < nfree && scans < CAP; idx++) {
            int i = freelist[idx];
            while (i != -1 && scans < CAP) {
                scans++;
                const float* lrow = smc + i*NQ;
                float l1 = INF, l2 = INF; int b1 = NQ;
                #pragma unroll
                for (int k = 0; k < NK; k++) {
                    int j = k*32 + lane;
                    if (j < NQ) {
                        float w = lrow[j] - vloc[k];
                        if (w < l1) { l2 = l1; l1 = w; b1 = j; }
                        else if (w < l2) l2 = w;
                    }
                }
                unsigned m1 = __reduce_min_sync(0xffffffffu, fmap(l1));
                unsigned bal = __ballot_sync(0xffffffffu, fmap(l1) == m1);
                int win = __ffs(bal) - 1;
                int j1  = __shfl_sync(0xffffffffu, b1, win);
                float u1 = finv(m1);
                float cand = (lane == win) ? l2 : l1;
                float u2 = finv(__reduce_min_sync(0xffffffffu, fmap(cand)));

                int i1 = row4col[j1];
                if (!(u1 < u2) && i1 != -1) break;   // degenerate tie -> Dijkstra
                if (lane == (j1 & 31) && u1 < u2) vloc[j1 >> 5] -= (u2 - u1);
                if (lane == 0) {
                    u[i] = u2;
                    row4col[j1] = i;
                    col4row[i]  = j1;
                    if (i1 != -1) col4row[i1] = -1;
                }
                __syncwarp();
                i = i1;
            }
        }
    }
    __syncwarp();

    // shortest augmenting path for whatever remains
    for (int curRow = 0; curRow < NT; curRow++) {
        if (col4row[curRow] != -1) continue;

        #pragma unroll
        for (int k = 0; k < NK; k++) shortest[k] = INF;
        unsigned sc = 0;
        int   i  = curRow;
        float mv = 0.f;
        int   nsteps = 0;
        int   sink = -1;

        while (true) {
            const float base = mv - u[i];
            const float* lrow = smc + i*NQ;

            float bv = INF; int bi = NQ;
            #pragma unroll
            for (int k = 0; k < NK; k++) {
                int j = k*32 + lane;
                if (j < NQ && !((sc >> k) & 1u)) {
                    float rr = base + lrow[j] - vloc[k];
                    if (rr < shortest[k]) { shortest[k] = rr; path[j] = i; }
                    if (shortest[k] < bv) { bv = shortest[k]; bi = j; }
                }
            }

            int fi = warp_argmin(bv, bi);
            mv = bv;

            if (lane == (fi & 31)) sc |= 1u << (fi >> 5);
            if (lane == 0) { selj[nsteps] = fi; selv[nsteps] = mv; }
            nsteps++;

            int r4 = row4col[fi];
            if (r4 == -1) { sink = fi; break; }
            i = r4;
        }

        __syncwarp();

        if (lane == 0) u[curRow] += mv;
        for (int s = lane; s < nsteps - 1; s += 32) {
            int i2 = row4col[selj[s]];
            u[i2] += mv - selv[s];
        }
        for (int s = 0; s < nsteps; s++) {
            int j = selj[s];
            if ((j & 31) == lane) vloc[j >> 5] -= mv - selv[s];
        }
        __syncwarp();

        if (lane == 0) {
            int j = sink;
            while (true) {
                int i2 = path[j];
                row4col[j] = i2;
                int nj = col4row[i2];
                col4row[i2] = j;
                j = nj;
                if (i2 == curRow) break;
            }
        }
        __syncwarp();
    }

    // emit indices sorted by query (rank counting)
    for (int t = lane; t < NT; t += 32) {
        int q = col4row[t];
        int rank = 0;
        #pragma unroll
        for (int t2 = 0; t2 < NT; t2++) rank += (col4row[t2] < q) ? 1 : 0;
        size_t base = (size_t)NROW * NCOL + (size_t)b * 2 * NT;
        out[base + rank]      = (float)q;
        out[base + NT + rank] = (float)t;
    }
}

// ---------------------------------------------------------
extern "C" void kernel_launch(void* const* d_in, const int* in_sizes, int n_in,
                              void* d_out, int out_size) {
    const float* pred_kp   = (const float*)d_in[0];  // (16,300,51)
    const float* pred_box  = (const float*)d_in[1];  // (16,300,6)
    const float* tgt_box   = (const float*)d_in[2];  // (16,50,6)
    const float* tgt_kp    = (const float*)d_in[3];  // (16,50,51)
    float* out = (float*)d_out;

    const int dyn_smem = DYN_FLOATS * (int)sizeof(float);   // 65900 B
    cudaFuncSetAttribute(fused_kernel, cudaFuncAttributeMaxDynamicSharedMemorySize, dyn_smem);

    fused_kernel<<<BS + GBX*GBY, TPB, dyn_smem>>>(pred_kp, pred_box, tgt_kp, tgt_box, out);
}

// round 10
// speedup vs baseline: 1.9887x; 1.1104x over previous
#include <cuda_runtime.h>
#include <cuda_bf16.h>

#define BS 16
#define NQ 300
#define NT 50
#define KP3 51          // 17 keypoints * 3
#define KPP 52          // padded (float4/ull2-friendly)
#define NCOL (BS*NT)    // 800
#define NROW (BS*NQ)    // 4800
#define NK 10           // columns per lane in LAP (10*32 >= 300)
#define CBLK 160        // cols per cost block == blockDim
#define TPB  160
#define NWARP (TPB/32)  // 5
#define RBLK 32         // rows per cost block
#define GBX  (NCOL/CBLK)   // 5
#define GBY  (NROW/RBLK)   // 150
#define TGRP 10         // targets per diag block
#define DIAG_BLKS (BS*(NT/TGRP))  // 80

#define DYN_FLOATS (NT*NQ)        // 15000 floats = 60000 B (cost path needs 9120)

typedef unsigned long long ull;

__device__ float g_lap[BS*NT*NQ];   // per-batch transposed diag cost [b][t][q]

#define ADD_F32X2(out, a, b) \
    asm("add.rn.f32x2 %0, %1, %2;" : "=l"(out) : "l"(a), "l"(b))

__device__ __forceinline__ float frcp(float x) {
    float r;
    asm("rcp.approx.f32 %0, %1;" : "=f"(r) : "f"(x));
    return r;
}
__device__ __forceinline__ unsigned fmap(float f) {
    unsigned u = __float_as_uint(f);
    return (u & 0x80000000u) ? ~u : (u | 0x80000000u);
}
__device__ __forceinline__ float finv(unsigned u) {
    return __uint_as_float((u & 0x80000000u) ? (u & 0x7FFFFFFFu) : ~u);
}
__device__ __forceinline__ int warp_argmin(float& bv, int bi) {
    unsigned bu  = fmap(bv);
    unsigned mvu = __reduce_min_sync(0xffffffffu, bu);
    unsigned bal = __ballot_sync(0xffffffffu, bu == mvu);
    int src = __ffs(bal) - 1;
    bv = finv(mvu);
    return __shfl_sync(0xffffffffu, bi, src);
}

// ---------------------------------------------------------
// Kernel 1: diagonal cost blocks -> g_lap. 80 blocks x 256 thr.
// block bb: batch bb/5, targets [tg*10, tg*10+10).
// ---------------------------------------------------------
__global__ void __launch_bounds__(256) diag_kernel(const float* __restrict__ pkp,
                                                   const float* __restrict__ pbox,
                                                   const float* __restrict__ tkp,
                                                   const float* __restrict__ tbox) {
    __shared__ __align__(16) float sdk[TGRP][KPP];
    __shared__ float stmn[TGRP][3], stmx[TGRP][3], stvol[TGRP];
    const int tid = threadIdx.x;
    const int b   = blockIdx.x / (NT/TGRP);
    const int tg  = blockIdx.x % (NT/TGRP);

    if (tid < TGRP) {
        int g = b*NT + tg*TGRP + tid;
        float sz[3], rsz[3];
        #pragma unroll
        for (int d = 0; d < 3; d++) {
            float ctr = tbox[g*6 + d];
            sz[d]     = tbox[g*6 + 3 + d];
            rsz[d]    = frcp(sz[d]);
            stmn[tid][d] = ctr - 0.5f*sz[d];
            stmx[tid][d] = ctr + 0.5f*sz[d];
        }
        stvol[tid] = sz[0]*sz[1]*sz[2];
        #pragma unroll
        for (int k = 0; k < KP3; k++) {
            int d = k - (k/3)*3;
            sdk[tid][k] = (tkp[(size_t)g*KP3 + k] - stmn[tid][d]) * rsz[d];
        }
        sdk[tid][KP3] = 0.f;
    }
    __syncthreads();

    for (int q = tid; q < NQ; q += 256) {
        float4 pk4[KPP/4];
        {
            float tmpk[KPP];
            const float* pr = pkp + (size_t)(b*NQ + q)*KP3;
            #pragma unroll
            for (int k = 0; k < KP3; k++) tmpk[k] = pr[k];
            tmpk[KP3] = 0.f;
            #pragma unroll
            for (int k4 = 0; k4 < KPP/4; k4++)
                pk4[k4] = make_float4(tmpk[4*k4], tmpk[4*k4+1], tmpk[4*k4+2], tmpk[4*k4+3]);
        }
        float pmn[3], pmx[3];
        #pragma unroll
        for (int d = 0; d < 3; d++) {
            float cc = pbox[(size_t)(b*NQ + q)*6 + d];
            float ss = pbox[(size_t)(b*NQ + q)*6 + 3 + d];
            pmn[d] = cc - 0.5f*ss; pmx[d] = cc + 0.5f*ss;
        }
        float vol1 = (pmx[0]-pmn[0])*(pmx[1]-pmn[1])*(pmx[2]-pmn[2]);

        #pragma unroll 2
        for (int tr = 0; tr < TGRP; tr++) {
            const float4* srow = (const float4*)sdk[tr];
            float s0 = 0.f, s1 = 0.f, s2 = 0.f, s3 = 0.f;
            #pragma unroll
            for (int k4 = 0; k4 < KPP/4; k4++) {
                float4 d4 = srow[k4];
                s0 += fabsf(pk4[k4].x - d4.x);
                s1 += fabsf(pk4[k4].y - d4.y);
                s2 += fabsf(pk4[k4].z - d4.z);
                s3 += fabsf(pk4[k4].w - d4.w);
            }
            float s = (s0 + s1) + (s2 + s3);
            float inter = 1.f, evol = 1.f;
            #pragma unroll
            for (int d = 0; d < 3; d++) {
                float tn = stmn[tr][d], tx = stmx[tr][d];
                inter *= fmaxf(fminf(pmx[d], tx) - fmaxf(pmn[d], tn), 0.f);
                evol  *= fmaxf(fmaxf(pmx[d], tx) - fminf(pmn[d], tn), 0.f);
            }
            float uni = vol1 + stvol[tr] - inter;
            float giou = inter*frcp(uni) - (evol - uni)*frcp(evol);
            g_lap[(size_t)(b*NT + tg*TGRP + tr)*NQ + q] = s - giou;
        }
    }
}

// ---------------------------------------------------------
// Kernel 2: fused. blocks [0,16): LAP (copy diag from g_lap + solve).
//           blocks [16,766): C matrix (160 cols x 32 rows each).
// ---------------------------------------------------------
__global__ void __launch_bounds__(TPB) fused_kernel(const float* __restrict__ pkp,
                                                    const float* __restrict__ pbox,
                                                    const float* __restrict__ tkp,
                                                    const float* __restrict__ tbox,
                                                    float* __restrict__ out) {
    extern __shared__ __align__(16) float dsm[];
    const int tid = threadIdx.x;

    if (blockIdx.x >= BS) {
        // ================== COST-MATRIX PATH ==================
        float* buf = dsm;
        const int cb = blockIdx.x - BS;
        const int c0 = (cb % GBX) * CBLK;
        const int r0 = (cb / GBX) * RBLK;
        const int c  = c0 + tid;

        // phase A: target slice -> registers
        for (int i = tid; i < CBLK*KP3; i += TPB) buf[i] = tkp[(size_t)c0*KP3 + i];
        for (int i = tid; i < CBLK*6;  i += TPB) buf[CBLK*KP3 + i] = tbox[(size_t)c0*6 + i];
        __syncthreads();

        ull  ndk[KPP/2];
        float tmn[3], tmx[3], tvol;
        {
            float sz[3], rsz[3];
            #pragma unroll
            for (int d = 0; d < 3; d++) {
                float ctr = buf[CBLK*KP3 + tid*6 + d];
                sz[d]     = buf[CBLK*KP3 + tid*6 + 3 + d];
                rsz[d]    = frcp(sz[d]);
                tmn[d] = ctr - 0.5f*sz[d];
                tmx[d] = ctr + 0.5f*sz[d];
            }
            tvol = sz[0]*sz[1]*sz[2];
            float dk[KPP];
            #pragma unroll
            for (int k = 0; k < KP3; k++) {
                int d = k - (k/3)*3;
                dk[k] = (buf[tid*KP3 + k] - tmn[d]) * rsz[d];
            }
            dk[KP3] = 0.f;
            #pragma unroll
            for (int k2 = 0; k2 < KPP/2; k2++) {
                float lo = -dk[2*k2], hi = -dk[2*k2+1];
                asm("mov.b64 %0, {%1, %2};" : "=l"(ndk[k2]) : "f"(lo), "f"(hi));
            }
        }
        __syncthreads();

        // phase B: pred rows padded to 52 + boxes
        for (int i = tid; i < RBLK*KPP; i += TPB) {
            int r = i / KPP, k = i - r*KPP;
            buf[i] = (k < KP3) ? pkp[(size_t)(r0+r)*KP3 + k] : 0.f;
        }
        for (int i = tid; i < RBLK*6; i += TPB) buf[RBLK*KPP + i] = pbox[(size_t)r0*6 + i];
        __syncthreads();

        const ull AMASK = 0x7FFFFFFF7FFFFFFFULL;
        #pragma unroll 2
        for (int r = 0; r < RBLK; r++) {
            const ulonglong2* prow = (const ulonglong2*)&buf[r*KPP];
            ull sacc[4] = {0, 0, 0, 0};
            #pragma unroll
            for (int k4 = 0; k4 < KPP/4; k4++) {
                ulonglong2 p = prow[k4];
                ull d0; ADD_F32X2(d0, p.x, ndk[2*k4]);
                d0 &= AMASK;
                ADD_F32X2(sacc[(2*k4)&3], sacc[(2*k4)&3], d0);
                ull d1; ADD_F32X2(d1, p.y, ndk[2*k4+1]);
                d1 &= AMASK;
                ADD_F32X2(sacc[(2*k4+1)&3], sacc[(2*k4+1)&3], d1);
            }
            ull sAB; ADD_F32X2(sAB, sacc[0], sacc[1]);
            ull sCD; ADD_F32X2(sCD, sacc[2], sacc[3]);
            ull st;  ADD_F32X2(st, sAB, sCD);
            float slo, shi;
            asm("mov.b64 {%0, %1}, %2;" : "=f"(slo), "=f"(shi) : "l"(st));
            float s = slo + shi;

            float pmn[3], pmx[3];
            #pragma unroll
            for (int d = 0; d < 3; d++) {
                float cc = buf[RBLK*KPP + r*6 + d];
                float ss = buf[RBLK*KPP + r*6 + 3 + d];
                pmn[d] = cc - 0.5f*ss; pmx[d] = cc + 0.5f*ss;
            }
            float vol1 = (pmx[0]-pmn[0])*(pmx[1]-pmn[1])*(pmx[2]-pmn[2]);
            float inter = 1.f, evol = 1.f;
            #pragma unroll
            for (int d = 0; d < 3; d++) {
                inter *= fmaxf(fminf(pmx[d], tmx[d]) - fmaxf(pmn[d], tmn[d]), 0.f);
                evol  *= fmaxf(fmaxf(pmx[d], tmx[d]) - fminf(pmn[d], tmn[d]), 0.f);
            }
            float uni = vol1 + tvol - inter;
            float giou = inter*frcp(uni) - (evol - uni)*frcp(evol);
            out[(size_t)(r0+r)*NCOL + c] = s - giou;
        }
        return;
    }

    // ================== LAP PATH (blocks 0..15) ==================
    float* smc = dsm;                      // [NT*NQ] diag cost block
    const int b    = blockIdx.x;
    const int lane = tid & 31;
    const int wid  = tid >> 5;
    const float INF = 3.0e38f;

    __shared__ float u[NT];
    __shared__ float rmin[NT];
    __shared__ int   ramin[NT];
    __shared__ int   path[NQ];
    __shared__ int   row4col[NQ];
    __shared__ int   col4row[NT];
    __shared__ int   selj[NQ + 2];
    __shared__ float selv[NQ + 2];
    __shared__ int   freelist[NT];

    // stage diag block from global (computed by diag_kernel)
    {
        const float4* src = (const float4*)&g_lap[(size_t)b*NT*NQ];
        float4* dst = (float4*)smc;
        #pragma unroll 4
        for (int i = tid; i < NT*NQ/4; i += TPB) dst[i] = src[i];
    }
    __syncthreads();

    // per-row min + argmin (5 warps over 50 rows)
    for (int row = wid; row < NT; row += NWARP) {
        const float* rp = smc + row*NQ;
        float bv = INF; int bi = NQ;
        for (int j = lane; j < NQ; j += 32) {
            float v = rp[j];
            if (v < bv) { bv = v; bi = j; }
        }
        int fi = warp_argmin(bv, bi);
        if (lane == 0) { rmin[row] = bv; ramin[row] = fi; }
    }
    __syncthreads();
    if (tid >= 32) return;                 // warp 0 solves alone

    float shortest[NK];
    float vloc[NK];

    for (int j = lane; j < NQ; j += 32) row4col[j] = -1;
    for (int t = lane; t < NT; t += 32) { u[t] = rmin[t]; col4row[t] = -1; }
    #pragma unroll
    for (int k = 0; k < NK; k++) vloc[k] = 0.f;
    __syncwarp();

    // greedy conflict-free assignment
    if (lane == 0) {
        #pragma unroll 1
        for (int i = 0; i < NT; i++) {
            int j = ramin[i];
            if (row4col[j] == -1) { row4col[j] = i; col4row[i] = j; }
        }
    }
    __syncwarp();

    // collect unassigned rows
    int nfree = 0;
    #pragma unroll
    for (int base = 0; base < NT; base += 32) {
        int t = base + lane;
        bool fr = (t < NT) && (col4row[t] == -1);
        unsigned m = __ballot_sync(0xffffffffu, fr);
        int pos = nfree + __popc(m & ((1u << lane) - 1u));
        if (fr) freelist[pos] = t;
        nfree += __popc(m);
    }
    __syncwarp();

    // JV augmenting row reduction (displacement chains)
    {
        int scans = 0;
        const int CAP = 8 * NT;
        for (int idx = 0; idx < nfree && scans < CAP; idx++) {
            int i = freelist[idx];
            while (i != -1 && scans < CAP) {
                scans++;
                const float* lrow = smc + i*NQ;
                float l1 = INF, l2 = INF; int b1 = NQ;
                #pragma unroll
                for (int k = 0; k < NK; k++) {
                    int j = k*32 + lane;
                    if (j < NQ) {
                        float w = lrow[j] - vloc[k];
                        if (w < l1) { l2 = l1; l1 = w; b1 = j; }
                        else if (w < l2) l2 = w;
                    }
                }
                unsigned m1 = __reduce_min_sync(0xffffffffu, fmap(l1));
                unsigned bal = __ballot_sync(0xffffffffu, fmap(l1) == m1);
                int win = __ffs(bal) - 1;
                int j1  = __shfl_sync(0xffffffffu, b1, win);
                float u1 = finv(m1);
                float cand = (lane == win) ? l2 : l1;
                float u2 = finv(__reduce_min_sync(0xffffffffu, fmap(cand)));

                int i1 = row4col[j1];
                if (!(u1 < u2) && i1 != -1) break;   // degenerate tie -> Dijkstra
                if (lane == (j1 & 31) && u1 < u2) vloc[j1 >> 5] -= (u2 - u1);
                if (lane == 0) {
                    u[i] = u2;
                    row4col[j1] = i;
                    col4row[i]  = j1;
                    if (i1 != -1) col4row[i1] = -1;
                }
                __syncwarp();
                i = i1;
            }
        }
    }
    __syncwarp();

    // shortest augmenting path for whatever remains
    for (int curRow = 0; curRow < NT; curRow++) {
        if (col4row[curRow] != -1) continue;

        #pragma unroll
        for (int k = 0; k < NK; k++) shortest[k] = INF;
        unsigned sc = 0;
        int   i  = curRow;
        float mv = 0.f;
        int   nsteps = 0;
        int   sink = -1;

        while (true) {
            const float base = mv - u[i];
            const float* lrow = smc + i*NQ;

            float bv = INF; int bi = NQ;
            #pragma unroll
            for (int k = 0; k < NK; k++) {
                int j = k*32 + lane;
                if (j < NQ && !((sc >> k) & 1u)) {
                    float rr = base + lrow[j] - vloc[k];
                    if (rr < shortest[k]) { shortest[k] = rr; path[j] = i; }
                    if (shortest[k] < bv) { bv = shortest[k]; bi = j; }
                }
            }

            int fi = warp_argmin(bv, bi);
            mv = bv;

            if (lane == (fi & 31)) sc |= 1u << (fi >> 5);
            if (lane == 0) { selj[nsteps] = fi; selv[nsteps] = mv; }
            nsteps++;

            int r4 = row4col[fi];
            if (r4 == -1) { sink = fi; break; }
            i = r4;
        }

        __syncwarp();

        if (lane == 0) u[curRow] += mv;
        for (int s = lane; s < nsteps - 1; s += 32) {
            int i2 = row4col[selj[s]];
            u[i2] += mv - selv[s];
        }
        for (int s = 0; s < nsteps; s++) {
            int j = selj[s];
            if ((j & 31) == lane) vloc[j >> 5] -= mv - selv[s];
        }
        __syncwarp();

        if (lane == 0) {
            int j = sink;
            while (true) {
                int i2 = path[j];
                row4col[j] = i2;
                int nj = col4row[i2];
                col4row[i2] = j;
                j = nj;
                if (i2 == curRow) break;
            }
        }
        __syncwarp();
    }

    // emit indices sorted by query (rank counting)
    for (int t = lane; t < NT; t += 32) {
        int q = col4row[t];
        int rank = 0;
        #pragma unroll
        for (int t2 = 0; t2 < NT; t2++) rank += (col4row[t2] < q) ? 1 : 0;
        size_t base = (size_t)NROW * NCOL + (size_t)b * 2 * NT;
        out[base + rank]      = (float)q;
        out[base + NT + rank] = (float)t;
    }
}

// ---------------------------------------------------------
extern "C" void kernel_launch(void* const* d_in, const int* in_sizes, int n_in,
                              void* d_out, int out_size) {
    const float* pred_kp   = (const float*)d_in[0];  // (16,300,51)
    const float* pred_box  = (const float*)d_in[1];  // (16,300,6)
    const float* tgt_box   = (const float*)d_in[2];  // (16,50,6)
    const float* tgt_kp    = (const float*)d_in[3];  // (16,50,51)
    float* out = (float*)d_out;

    const int dyn_smem = DYN_FLOATS * (int)sizeof(float);   // 60000 B
    cudaFuncSetAttribute(fused_kernel, cudaFuncAttributeMaxDynamicSharedMemorySize, dyn_smem);

    diag_kernel<<<DIAG_BLKS, 256>>>(pred_kp, pred_box, tgt_kp, tgt_box);
    fused_kernel<<<BS + GBX*GBY, TPB, dyn_smem>>>(pred_kp, pred_box, tgt_kp, tgt_box, out);
}

// round 11
// speedup vs baseline: 2.0424x; 1.0270x over previous
#include <cuda_runtime.h>
#include <cuda_bf16.h>

#define BS 16
#define NQ 300
#define NT 50
#define KP3 51          // 17 keypoints * 3
#define KPP 52          // padded (float4/ull2-friendly)
#define NCOL (BS*NT)    // 800
#define NROW (BS*NQ)    // 4800
#define NK 10           // columns per lane in LAP (10*32 >= 300)
#define CBLK 160        // cols per cost block == blockDim
#define TPB  160
#define NWARP (TPB/32)  // 5
#define RBLK 32         // rows per cost block
#define GBX  (NCOL/CBLK)   // 5
#define GBY  (NROW/RBLK)   // 150
#define TGRP 10         // targets per diag block
#define DIAG_BLKS (BS*(NT/TGRP))  // 80
#define SCANBUDGET 160  // per-warp JV scan budget

// dynamic smem: smc[NT*NQ] floats + vown[NQ] ull
#define DYN_BYTES (NT*NQ*4 + NQ*8)   // 62400 B (cost path needs 36480)

typedef unsigned long long ull;

__device__ float g_lap[BS*NT*NQ];   // per-batch transposed diag cost [b][t][q]

#define ADD_F32X2(out, a, b) \
    asm("add.rn.f32x2 %0, %1, %2;" : "=l"(out) : "l"(a), "l"(b))

__device__ __forceinline__ float frcp(float x) {
    float r;
    asm("rcp.approx.f32 %0, %1;" : "=f"(r) : "f"(x));
    return r;
}
__device__ __forceinline__ unsigned fmap(float f) {
    unsigned u = __float_as_uint(f);
    return (u & 0x80000000u) ? ~u : (u | 0x80000000u);
}
__device__ __forceinline__ float finv(unsigned u) {
    return __uint_as_float((u & 0x80000000u) ? (u & 0x7FFFFFFFu) : ~u);
}
__device__ __forceinline__ int warp_argmin(float& bv, int bi) {
    unsigned bu  = fmap(bv);
    unsigned mvu = __reduce_min_sync(0xffffffffu, bu);
    unsigned bal = __ballot_sync(0xffffffffu, bu == mvu);
    int src = __ffs(bal) - 1;
    bv = finv(mvu);
    return __shfl_sync(0xffffffffu, bi, src);
}
__device__ __forceinline__ ull packvo(float v, int owner) {
    return ((ull)__float_as_uint(v) << 32) | (unsigned)owner;
}
__device__ __forceinline__ float vo_v(ull p) { return __uint_as_float((unsigned)(p >> 32)); }
__device__ __forceinline__ int   vo_o(ull p) { return (int)(unsigned)(p & 0xffffffffu); }

// ---------------------------------------------------------
// Kernel 1: diagonal cost blocks -> g_lap. 80 blocks x 256 thr.
// ---------------------------------------------------------
__global__ void __launch_bounds__(256) diag_kernel(const float* __restrict__ pkp,
                                                   const float* __restrict__ pbox,
                                                   const float* __restrict__ tkp,
                                                   const float* __restrict__ tbox) {
    __shared__ __align__(16) float sdk[TGRP][KPP];
    __shared__ float stmn[TGRP][3], stmx[TGRP][3], stvol[TGRP];
    const int tid = threadIdx.x;
    const int b   = blockIdx.x / (NT/TGRP);
    const int tg  = blockIdx.x % (NT/TGRP);

    if (tid < TGRP) {
        int g = b*NT + tg*TGRP + tid;
        float sz[3], rsz[3];
        #pragma unroll
        for (int d = 0; d < 3; d++) {
            float ctr = tbox[g*6 + d];
            sz[d]     = tbox[g*6 + 3 + d];
            rsz[d]    = frcp(sz[d]);
            stmn[tid][d] = ctr - 0.5f*sz[d];
            stmx[tid][d] = ctr + 0.5f*sz[d];
        }
        stvol[tid] = sz[0]*sz[1]*sz[2];
        #pragma unroll
        for (int k = 0; k < KP3; k++) {
            int d = k - (k/3)*3;
            sdk[tid][k] = (tkp[(size_t)g*KP3 + k] - stmn[tid][d]) * rsz[d];
        }
        sdk[tid][KP3] = 0.f;
    }
    __syncthreads();

    for (int q = tid; q < NQ; q += 256) {
        float4 pk4[KPP/4];
        {
            float tmpk[KPP];
            const float* pr = pkp + (size_t)(b*NQ + q)*KP3;
            #pragma unroll
            for (int k = 0; k < KP3; k++) tmpk[k] = pr[k];
            tmpk[KP3] = 0.f;
            #pragma unroll
            for (int k4 = 0; k4 < KPP/4; k4++)
                pk4[k4] = make_float4(tmpk[4*k4], tmpk[4*k4+1], tmpk[4*k4+2], tmpk[4*k4+3]);
        }
        float pmn[3], pmx[3];
        #pragma unroll
        for (int d = 0; d < 3; d++) {
            float cc = pbox[(size_t)(b*NQ + q)*6 + d];
            float ss = pbox[(size_t)(b*NQ + q)*6 + 3 + d];
            pmn[d] = cc - 0.5f*ss; pmx[d] = cc + 0.5f*ss;
        }
        float vol1 = (pmx[0]-pmn[0])*(pmx[1]-pmn[1])*(pmx[2]-pmn[2]);

        #pragma unroll 2
        for (int tr = 0; tr < TGRP; tr++) {
            const float4* srow = (const float4*)sdk[tr];
            float s0 = 0.f, s1 = 0.f, s2 = 0.f, s3 = 0.f;
            #pragma unroll
            for (int k4 = 0; k4 < KPP/4; k4++) {
                float4 d4 = srow[k4];
                s0 += fabsf(pk4[k4].x - d4.x);
                s1 += fabsf(pk4[k4].y - d4.y);
                s2 += fabsf(pk4[k4].z - d4.z);
                s3 += fabsf(pk4[k4].w - d4.w);
            }
            float s = (s0 + s1) + (s2 + s3);
            float inter = 1.f, evol = 1.f;
            #pragma unroll
            for (int d = 0; d < 3; d++) {
                float tn = stmn[tr][d], tx = stmx[tr][d];
                inter *= fmaxf(fminf(pmx[d], tx) - fmaxf(pmn[d], tn), 0.f);
                evol  *= fmaxf(fmaxf(pmx[d], tx) - fminf(pmn[d], tn), 0.f);
            }
            float uni = vol1 + stvol[tr] - inter;
            float giou = inter*frcp(uni) - (evol - uni)*frcp(evol);
            g_lap[(size_t)(b*NT + tg*TGRP + tr)*NQ + q] = s - giou;
        }
    }
}

// ---------------------------------------------------------
// Kernel 2: fused. blocks [0,16): LAP.  blocks [16,766): C matrix.
// ---------------------------------------------------------
__global__ void __launch_bounds__(TPB) fused_kernel(const float* __restrict__ pkp,
                                                    const float* __restrict__ pbox,
                                                    const float* __restrict__ tkp,
                                                    const float* __restrict__ tbox,
                                                    float* __restrict__ out) {
    extern __shared__ __align__(16) float dsm[];
    const int tid = threadIdx.x;

    if (blockIdx.x >= BS) {
        // ================== COST-MATRIX PATH ==================
        float* buf = dsm;
        const int cb = blockIdx.x - BS;
        const int c0 = (cb % GBX) * CBLK;
        const int r0 = (cb / GBX) * RBLK;
        const int c  = c0 + tid;

        for (int i = tid; i < CBLK*KP3; i += TPB) buf[i] = tkp[(size_t)c0*KP3 + i];
        for (int i = tid; i < CBLK*6;  i += TPB) buf[CBLK*KP3 + i] = tbox[(size_t)c0*6 + i];
        __syncthreads();

        ull  ndk[KPP/2];
        float tmn[3], tmx[3], tvol;
        {
            float sz[3], rsz[3];
            #pragma unroll
            for (int d = 0; d < 3; d++) {
                float ctr = buf[CBLK*KP3 + tid*6 + d];
                sz[d]     = buf[CBLK*KP3 + tid*6 + 3 + d];
                rsz[d]    = frcp(sz[d]);
                tmn[d] = ctr - 0.5f*sz[d];
                tmx[d] = ctr + 0.5f*sz[d];
            }
            tvol = sz[0]*sz[1]*sz[2];
            float dk[KPP];
            #pragma unroll
            for (int k = 0; k < KP3; k++) {
                int d = k - (k/3)*3;
                dk[k] = (buf[tid*KP3 + k] - tmn[d]) * rsz[d];
            }
            dk[KP3] = 0.f;
            #pragma unroll
            for (int k2 = 0; k2 < KPP/2; k2++) {
                float lo = -dk[2*k2], hi = -dk[2*k2+1];
                asm("mov.b64 %0, {%1, %2};" : "=l"(ndk[k2]) : "f"(lo), "f"(hi));
            }
        }
        __syncthreads();

        for (int i = tid; i < RBLK*KPP; i += TPB) {
            int r = i / KPP, k = i - r*KPP;
            buf[i] = (k < KP3) ? pkp[(size_t)(r0+r)*KP3 + k] : 0.f;
        }
        for (int i = tid; i < RBLK*6; i += TPB) buf[RBLK*KPP + i] = pbox[(size_t)r0*6 + i];
        __syncthreads();

        const ull AMASK = 0x7FFFFFFF7FFFFFFFULL;
        #pragma unroll 2
        for (int r = 0; r < RBLK; r++) {
            const ulonglong2* prow = (const ulonglong2*)&buf[r*KPP];
            ull sacc[4] = {0, 0, 0, 0};
            #pragma unroll
            for (int k4 = 0; k4 < KPP/4; k4++) {
                ulonglong2 p = prow[k4];
                ull d0; ADD_F32X2(d0, p.x, ndk[2*k4]);
                d0 &= AMASK;
                ADD_F32X2(sacc[(2*k4)&3], sacc[(2*k4)&3], d0);
                ull d1; ADD_F32X2(d1, p.y, ndk[2*k4+1]);
                d1 &= AMASK;
                ADD_F32X2(sacc[(2*k4+1)&3], sacc[(2*k4+1)&3], d1);
            }
            ull sAB; ADD_F32X2(sAB, sacc[0], sacc[1]);
            ull sCD; ADD_F32X2(sCD, sacc[2], sacc[3]);
            ull st;  ADD_F32X2(st, sAB, sCD);
            float slo, shi;
            asm("mov.b64 {%0, %1}, %2;" : "=f"(slo), "=f"(shi) : "l"(st));
            float s = slo + shi;

            float pmn[3], pmx[3];
            #pragma unroll
            for (int d = 0; d < 3; d++) {
                float cc = buf[RBLK*KPP + r*6 + d];
                float ss = buf[RBLK*KPP + r*6 + 3 + d];
                pmn[d] = cc - 0.5f*ss; pmx[d] = cc + 0.5f*ss;
            }
            float vol1 = (pmx[0]-pmn[0])*(pmx[1]-pmn[1])*(pmx[2]-pmn[2]);
            float inter = 1.f, evol = 1.f;
            #pragma unroll
            for (int d = 0; d < 3; d++) {
                inter *= fmaxf(fminf(pmx[d], tmx[d]) - fmaxf(pmn[d], tmn[d]), 0.f);
                evol  *= fmaxf(fmaxf(pmx[d], tmx[d]) - fminf(pmn[d], tmn[d]), 0.f);
            }
            float uni = vol1 + tvol - inter;
            float giou = inter*frcp(uni) - (evol - uni)*frcp(evol);
            out[(size_t)(r0+r)*NCOL + c] = s - giou;
        }
        return;
    }

    // ================== LAP PATH (blocks 0..15) ==================
    float* smc = dsm;                                  // [NT*NQ]
    ull*   vown = (ull*)(dsm + NT*NQ);                 // [NQ] packed (v, owner)
    volatile ull* vvown = (volatile ull*)vown;
    const int b    = blockIdx.x;
    const int lane = tid & 31;
    const int wid  = tid >> 5;
    const float INF = 3.0e38f;

    __shared__ float u[NT];
    __shared__ float rmin[NT];
    __shared__ int   ramin[NT];
    __shared__ int   path[NQ];
    __shared__ int   row4col[NQ];
    __shared__ int   col4row[NT];
    __shared__ int   selj[NQ + 2];
    __shared__ float selv[NQ + 2];
    __shared__ int   freelist[NT];
    __shared__ int   qh, nfree_sh;

    // stage diag block from global
    {
        const float4* src = (const float4*)&g_lap[(size_t)b*NT*NQ];
        float4* dst = (float4*)smc;
        #pragma unroll 4
        for (int i = tid; i < NT*NQ/4; i += TPB) dst[i] = src[i];
    }
    for (int j = tid; j < NQ; j += TPB) vown[j] = packvo(0.f, -1);
    if (tid < NT) col4row[tid] = -1;
    if (tid == 0) qh = 0;
    __syncthreads();

    // per-row min + argmin (5 warps over 50 rows); u init
    for (int row = wid; row < NT; row += NWARP) {
        const float* rp = smc + row*NQ;
        float bv = INF; int bi = NQ;
        for (int j = lane; j < NQ; j += 32) {
            float v = rp[j];
            if (v < bv) { bv = v; bi = j; }
        }
        int fi = warp_argmin(bv, bi);
        if (lane == 0) { rmin[row] = bv; ramin[row] = fi; u[row] = bv; }
    }
    __syncthreads();

    // warp 0: greedy conflict-free assignment + freelist
    if (tid < 32) {
        if (lane == 0) {
            #pragma unroll 1
            for (int i = 0; i < NT; i++) {
                int j = ramin[i];
                if (vo_o(vown[j]) == -1) { vown[j] = packvo(0.f, i); col4row[i] = j; }
            }
        }
        __syncwarp();
        int nfree = 0;
        #pragma unroll
        for (int base = 0; base < NT; base += 32) {
            int t = base + lane;
            bool fr = (t < NT) && (col4row[t] == -1);
            unsigned m = __ballot_sync(0xffffffffu, fr);
            int pos = nfree + __popc(m & ((1u << lane) - 1u));
            if (fr) freelist[pos] = t;
            nfree += __popc(m);
        }
        if (lane == 0) nfree_sh = nfree;
    }
    __syncthreads();

    // ---- PARALLEL JV augmenting row reduction: all 5 warps ----
    {
        const int nfree = nfree_sh;
        int budget = SCANBUDGET;
        for (;;) {
            int idx = 0;
            if (lane == 0) idx = atomicAdd(&qh, 1);
            idx = __shfl_sync(0xffffffffu, idx, 0);
            if (idx >= nfree || budget <= 0) break;
            int i = freelist[idx];

            bool alive = true;
            while (alive && budget > 0) {
                budget--;
                // scan row i over packed (v, owner)
                const float* lrow = smc + i*NQ;
                float l1 = INF, l2 = INF; int b1 = NQ; ull p1 = 0;
                #pragma unroll
                for (int k = 0; k < NK; k++) {
                    int j = k*32 + lane;
                    if (j < NQ) {
                        ull pv = vvown[j];
                        float w = lrow[j] - vo_v(pv);
                        if (w < l1) { l2 = l1; l1 = w; b1 = j; p1 = pv; }
                        else if (w < l2) l2 = w;
                    }
                }
                unsigned m1 = __reduce_min_sync(0xffffffffu, fmap(l1));
                unsigned bal = __ballot_sync(0xffffffffu, fmap(l1) == m1);
                int win = __ffs(bal) - 1;
                int j1  = __shfl_sync(0xffffffffu, b1, win);
                ull p64 = __shfl_sync(0xffffffffu, p1, win);
                float u1 = finv(m1);
                float cand = (lane == win) ? l2 : l1;
                float u2 = finv(__reduce_min_sync(0xffffffffu, fmap(cand)));

                int owner1 = vo_o(p64);
                if (!(u1 < u2) && owner1 != -1) { alive = false; break; }  // tie -> Dijkstra

                int ok = 0;
                if (lane == win) {
                    float vnew = vo_v(p64) - (u2 - u1);
                    ok = (atomicCAS(&vown[j1], p64, packvo(vnew, i)) == p64);
                }
                ok = __shfl_sync(0xffffffffu, ok, win);
                if (!ok) continue;      // stale view; rescan

                if (lane == win) {
                    u[i] = u2;
                    col4row[i] = j1;
                    if (owner1 != -1) col4row[owner1] = -1;
                }
                __syncwarp();
                if (owner1 == -1) alive = false;   // chain terminated at free column
                else i = owner1;                   // continue with displaced row
            }
        }
    }
    __syncthreads();
    if (tid >= 32) return;                 // warp 0 finishes alone

    // extract v / row4col for Dijkstra
    float vloc[NK];
    #pragma unroll
    for (int k = 0; k < NK; k++) {
        int j = k*32 + lane;
        vloc[k] = (j < NQ) ? vo_v(vown[j]) : 0.f;
    }
    for (int j = lane; j < NQ; j += 32) row4col[j] = vo_o(vown[j]);
    __syncwarp();

    float shortest[NK];

    // shortest augmenting path for whatever remains (exact backstop)
    for (int curRow = 0; curRow < NT; curRow++) {
        if (col4row[curRow] != -1) continue;

        #pragma unroll
        for (int k = 0; k < NK; k++) shortest[k] = INF;
        unsigned sc = 0;
        int   i  = curRow;
        float mv = 0.f;
        int   nsteps = 0;
        int   sink = -1;

        while (true) {
            const float base = mv - u[i];
            const float* lrow = smc + i*NQ;

            float bv = INF; int bi = NQ;
            #pragma unroll
            for (int k = 0; k < NK; k++) {
                int j = k*32 + lane;
                if (j < NQ && !((sc >> k) & 1u)) {
                    float rr = base + lrow[j] - vloc[k];
                    if (rr < shortest[k]) { shortest[k] = rr; path[j] = i; }
                    if (shortest[k] < bv) { bv = shortest[k]; bi = j; }
                }
            }

            int fi = warp_argmin(bv, bi);
            mv = bv;

            if (lane == (fi & 31)) sc |= 1u << (fi >> 5);
            if (lane == 0) { selj[nsteps] = fi; selv[nsteps] = mv; }
            nsteps++;

            int r4 = row4col[fi];
            if (r4 == -1) { sink = fi; break; }
            i = r4;
        }

        __syncwarp();

        if (lane == 0) u[curRow] += mv;
        for (int s = lane; s < nsteps - 1; s += 32) {
            int i2 = row4col[selj[s]];
            u[i2] += mv - selv[s];
        }
        for (int s = 0; s < nsteps; s++) {
            int j = selj[s];
            if ((j & 31) == lane) vloc[j >> 5] -= mv - selv[s];
        }
        __syncwarp();

        if (lane == 0) {
            int j = sink;
            while (true) {
                int i2 = path[j];
                row4col[j] = i2;
                int nj = col4row[i2];
                col4row[i2] = j;
                j = nj;
                if (i2 == curRow) break;
            }
        }
        __syncwarp();
    }

    // emit indices sorted by query (rank counting)
    for (int t = lane; t < NT; t += 32) {
        int q = col4row[t];
        int rank = 0;
        #pragma unroll
        for (int t2 = 0; t2 < NT; t2++) rank += (col4row[t2] < q) ? 1 : 0;
        size_t base = (size_t)NROW * NCOL + (size_t)b * 2 * NT;
        out[base + rank]      = (float)q;
        out[base + NT + rank] = (float)t;
    }
}

// ---------------------------------------------------------
extern "C" void kernel_launch(void* const* d_in, const int* in_sizes, int n_in,
                              void* d_out, int out_size) {
    const float* pred_kp   = (const float*)d_in[0];  // (16,300,51)
    const float* pred_box  = (const float*)d_in[1];  // (16,300,6)
    const float* tgt_box   = (const float*)d_in[2];  // (16,50,6)
    const float* tgt_kp    = (const float*)d_in[3];  // (16,50,51)
    float* out = (float*)d_out;

    cudaFuncSetAttribute(fused_kernel, cudaFuncAttributeMaxDynamicSharedMemorySize, DYN_BYTES);

    diag_kernel<<<DIAG_BLKS, 256>>>(pred_kp, pred_box, tgt_kp, tgt_box);
    fused_kernel<<<BS + GBX*GBY, TPB, DYN_BYTES>>>(pred_kp, pred_box, tgt_kp, tgt_box, out);
}

// round 12
// speedup vs baseline: 2.1182x; 1.0371x over previous
#include <cuda_runtime.h>
#include <cuda_bf16.h>

#define BS 16
#define NQ 300
#define NT 50
#define KP3 51          // 17 keypoints * 3
#define KPP 52          // padded (float4/ull2-friendly)
#define NCOL (BS*NT)    // 800
#define NROW (BS*NQ)    // 4800
#define NK 10           // columns per lane in LAP (10*32 >= 300)
#define CBLK 160        // cols per cost block == blockDim
#define TPB  160
#define NWARP (TPB/32)  // 5
#define RBLK 64         // rows per cost block
#define GBX  (NCOL/CBLK)   // 5
#define GBY  (NROW/RBLK)   // 75
#define ACH  80         // phase-A chunk (columns)
#define TGRP 10         // targets per diag block
#define DIAG_BLKS (BS*(NT/TGRP))  // 80
#define SCANBUDGET 160  // per-warp JV scan budget

// dynamic smem (floats): cost staging only
// phase A chunk: ACH*(KP3+6) = 4560 ; phase B: RBLK*(KPP+6) = 3712
#define DYN_FLOATS 4560
#define DYN_BYTES (DYN_FLOATS*4)   // 18240 B

typedef unsigned long long ull;

__device__ float g_lap[BS*NT*NQ];   // per-batch transposed diag cost [b][t][q]

#define ADD_F32X2(out, a, b) \
    asm("add.rn.f32x2 %0, %1, %2;" : "=l"(out) : "l"(a), "l"(b))

__device__ __forceinline__ float frcp(float x) {
    float r;
    asm("rcp.approx.f32 %0, %1;" : "=f"(r) : "f"(x));
    return r;
}
__device__ __forceinline__ unsigned fmap(float f) {
    unsigned u = __float_as_uint(f);
    return (u & 0x80000000u) ? ~u : (u | 0x80000000u);
}
__device__ __forceinline__ float finv(unsigned u) {
    return __uint_as_float((u & 0x80000000u) ? (u & 0x7FFFFFFFu) : ~u);
}
__device__ __forceinline__ int warp_argmin(float& bv, int bi) {
    unsigned bu  = fmap(bv);
    unsigned mvu = __reduce_min_sync(0xffffffffu, bu);
    unsigned bal = __ballot_sync(0xffffffffu, bu == mvu);
    int src = __ffs(bal) - 1;
    bv = finv(mvu);
    return __shfl_sync(0xffffffffu, bi, src);
}
__device__ __forceinline__ ull packvo(float v, int owner) {
    return ((ull)__float_as_uint(v) << 32) | (unsigned)owner;
}
__device__ __forceinline__ float vo_v(ull p) { return __uint_as_float((unsigned)(p >> 32)); }
__device__ __forceinline__ int   vo_o(ull p) { return (int)(unsigned)(p & 0xffffffffu); }

// ---------------------------------------------------------
// Kernel 1: diagonal cost blocks -> g_lap. 80 blocks x 256 thr.
// ---------------------------------------------------------
__global__ void __launch_bounds__(256) diag_kernel(const float* __restrict__ pkp,
                                                   const float* __restrict__ pbox,
                                                   const float* __restrict__ tkp,
                                                   const float* __restrict__ tbox) {
    __shared__ __align__(16) float sdk[TGRP][KPP];
    __shared__ float stmn[TGRP][3], stmx[TGRP][3], stvol[TGRP];
    const int tid = threadIdx.x;
    const int b   = blockIdx.x / (NT/TGRP);
    const int tg  = blockIdx.x % (NT/TGRP);

    if (tid < TGRP) {
        int g = b*NT + tg*TGRP + tid;
        float sz[3], rsz[3];
        #pragma unroll
        for (int d = 0; d < 3; d++) {
            float ctr = tbox[g*6 + d];
            sz[d]     = tbox[g*6 + 3 + d];
            rsz[d]    = frcp(sz[d]);
            stmn[tid][d] = ctr - 0.5f*sz[d];
            stmx[tid][d] = ctr + 0.5f*sz[d];
        }
        stvol[tid] = sz[0]*sz[1]*sz[2];
        #pragma unroll
        for (int k = 0; k < KP3; k++) {
            int d = k - (k/3)*3;
            sdk[tid][k] = (tkp[(size_t)g*KP3 + k] - stmn[tid][d]) * rsz[d];
        }
        sdk[tid][KP3] = 0.f;
    }
    __syncthreads();

    for (int q = tid; q < NQ; q += 256) {
        float4 pk4[KPP/4];
        {
            float tmpk[KPP];
            const float* pr = pkp + (size_t)(b*NQ + q)*KP3;
            #pragma unroll
            for (int k = 0; k < KP3; k++) tmpk[k] = pr[k];
            tmpk[KP3] = 0.f;
            #pragma unroll
            for (int k4 = 0; k4 < KPP/4; k4++)
                pk4[k4] = make_float4(tmpk[4*k4], tmpk[4*k4+1], tmpk[4*k4+2], tmpk[4*k4+3]);
        }
        float pmn[3], pmx[3];
        #pragma unroll
        for (int d = 0; d < 3; d++) {
            float cc = pbox[(size_t)(b*NQ + q)*6 + d];
            float ss = pbox[(size_t)(b*NQ + q)*6 + 3 + d];
            pmn[d] = cc - 0.5f*ss; pmx[d] = cc + 0.5f*ss;
        }
        float vol1 = (pmx[0]-pmn[0])*(pmx[1]-pmn[1])*(pmx[2]-pmn[2]);

        #pragma unroll 2
        for (int tr = 0; tr < TGRP; tr++) {
            const float4* srow = (const float4*)sdk[tr];
            float s0 = 0.f, s1 = 0.f, s2 = 0.f, s3 = 0.f;
            #pragma unroll
            for (int k4 = 0; k4 < KPP/4; k4++) {
                float4 d4 = srow[k4];
                s0 += fabsf(pk4[k4].x - d4.x);
                s1 += fabsf(pk4[k4].y - d4.y);
                s2 += fabsf(pk4[k4].z - d4.z);
                s3 += fabsf(pk4[k4].w - d4.w);
            }
            float s = (s0 + s1) + (s2 + s3);
            float inter = 1.f, evol = 1.f;
            #pragma unroll
            for (int d = 0; d < 3; d++) {
                float tn = stmn[tr][d], tx = stmx[tr][d];
                inter *= fmaxf(fminf(pmx[d], tx) - fmaxf(pmn[d], tn), 0.f);
                evol  *= fmaxf(fmaxf(pmx[d], tx) - fminf(pmn[d], tn), 0.f);
            }
            float uni = vol1 + stvol[tr] - inter;
            float giou = inter*frcp(uni) - (evol - uni)*frcp(evol);
            g_lap[(size_t)(b*NT + tg*TGRP + tr)*NQ + q] = s - giou;
        }
    }
}

// ---------------------------------------------------------
// Kernel 2: fused, single wave (391 blocks @ 4 CTAs/SM).
// blocks [0,16): LAP (reads g_lap via L1).  blocks [16,391): C matrix.
// ---------------------------------------------------------
__global__ void __launch_bounds__(TPB) fused_kernel(const float* __restrict__ pkp,
                                                    const float* __restrict__ pbox,
                                                    const float* __restrict__ tkp,
                                                    const float* __restrict__ tbox,
                                                    float* __restrict__ out) {
    extern __shared__ __align__(16) float dsm[];
    const int tid = threadIdx.x;

    if (blockIdx.x >= BS) {
        // ================== COST-MATRIX PATH ==================
        float* buf = dsm;
        const int cb = blockIdx.x - BS;
        const int c0 = (cb % GBX) * CBLK;
        const int r0 = (cb / GBX) * RBLK;
        const int c  = c0 + tid;

        ull  ndk[KPP/2];
        float tmn[3], tmx[3], tvol = 0.f;

        // phase A: two chunks of 80 target columns -> registers
        #pragma unroll 1
        for (int ch = 0; ch < 2; ch++) {
            const int cc0 = ch * ACH;
            for (int i = tid; i < ACH*KP3; i += TPB) buf[i] = tkp[(size_t)(c0+cc0)*KP3 + i];
            for (int i = tid; i < ACH*6;  i += TPB) buf[ACH*KP3 + i] = tbox[(size_t)(c0+cc0)*6 + i];
            __syncthreads();
            if (tid >= cc0 && tid < cc0 + ACH) {
                const int lt = tid - cc0;
                float sz[3], rsz[3];
                #pragma unroll
                for (int d = 0; d < 3; d++) {
                    float ctr = buf[ACH*KP3 + lt*6 + d];
                    sz[d]     = buf[ACH*KP3 + lt*6 + 3 + d];
                    rsz[d]    = frcp(sz[d]);
                    tmn[d] = ctr - 0.5f*sz[d];
                    tmx[d] = ctr + 0.5f*sz[d];
                }
                tvol = sz[0]*sz[1]*sz[2];
                float dk[KPP];
                #pragma unroll
                for (int k = 0; k < KP3; k++) {
                    int d = k - (k/3)*3;
                    dk[k] = (buf[lt*KP3 + k] - tmn[d]) * rsz[d];
                }
                dk[KP3] = 0.f;
                #pragma unroll
                for (int k2 = 0; k2 < KPP/2; k2++) {
                    float lo = -dk[2*k2], hi = -dk[2*k2+1];
                    asm("mov.b64 %0, {%1, %2};" : "=l"(ndk[k2]) : "f"(lo), "f"(hi));
                }
            }
            __syncthreads();
        }

        // phase B: pred rows padded to 52 + boxes
        for (int i = tid; i < RBLK*KPP; i += TPB) {
            int r = i / KPP, k = i - r*KPP;
            buf[i] = (k < KP3) ? pkp[(size_t)(r0+r)*KP3 + k] : 0.f;
        }
        for (int i = tid; i < RBLK*6; i += TPB) buf[RBLK*KPP + i] = pbox[(size_t)r0*6 + i];
        __syncthreads();

        const ull AMASK = 0x7FFFFFFF7FFFFFFFULL;
        #pragma unroll 2
        for (int r = 0; r < RBLK; r++) {
            const ulonglong2* prow = (const ulonglong2*)&buf[r*KPP];
            ull sacc[4] = {0, 0, 0, 0};
            #pragma unroll
            for (int k4 = 0; k4 < KPP/4; k4++) {
                ulonglong2 p = prow[k4];
                ull d0; ADD_F32X2(d0, p.x, ndk[2*k4]);
                d0 &= AMASK;
                ADD_F32X2(sacc[(2*k4)&3], sacc[(2*k4)&3], d0);
                ull d1; ADD_F32X2(d1, p.y, ndk[2*k4+1]);
                d1 &= AMASK;
                ADD_F32X2(sacc[(2*k4+1)&3], sacc[(2*k4+1)&3], d1);
            }
            ull sAB; ADD_F32X2(sAB, sacc[0], sacc[1]);
            ull sCD; ADD_F32X2(sCD, sacc[2], sacc[3]);
            ull st;  ADD_F32X2(st, sAB, sCD);
            float slo, shi;
            asm("mov.b64 {%0, %1}, %2;" : "=f"(slo), "=f"(shi) : "l"(st));
            float s = slo + shi;

            float pmn[3], pmx[3];
            #pragma unroll
            for (int d = 0; d < 3; d++) {
                float cc = buf[RBLK*KPP + r*6 + d];
                float ss = buf[RBLK*KPP + r*6 + 3 + d];
                pmn[d] = cc - 0.5f*ss; pmx[d] = cc + 0.5f*ss;
            }
            float vol1 = (pmx[0]-pmn[0])*(pmx[1]-pmn[1])*(pmx[2]-pmn[2]);
            float inter = 1.f, evol = 1.f;
            #pragma unroll
            for (int d = 0; d < 3; d++) {
                inter *= fmaxf(fminf(pmx[d], tmx[d]) - fmaxf(pmn[d], tmn[d]), 0.f);
                evol  *= fmaxf(fmaxf(pmx[d], tmx[d]) - fminf(pmn[d], tmn[d]), 0.f);
            }
            float uni = vol1 + tvol - inter;
            float giou = inter*frcp(uni) - (evol - uni)*frcp(evol);
            out[(size_t)(r0+r)*NCOL + c] = s - giou;
        }
        return;
    }

    // ================== LAP PATH (blocks 0..15) ==================
    // cost rows read directly from g_lap (L1-resident after first pass)
    const int b    = blockIdx.x;
    const int lane = tid & 31;
    const int wid  = tid >> 5;
    const float INF = 3.0e38f;
    const float* lbase = &g_lap[(size_t)b*NT*NQ];

    __shared__ ull   vown[NQ];          // packed (v, owner)
    __shared__ float u[NT];
    __shared__ float rmin[NT];
    __shared__ int   ramin[NT];
    __shared__ int   path[NQ];
    __shared__ int   row4col[NQ];
    __shared__ int   col4row[NT];
    __shared__ int   selj[NQ + 2];
    __shared__ float selv[NQ + 2];
    __shared__ int   freelist[NT];
    __shared__ int   qh, nfree_sh;
    volatile ull* vvown = (volatile ull*)vown;

    for (int j = tid; j < NQ; j += TPB) vown[j] = packvo(0.f, -1);
    if (tid < NT) col4row[tid] = -1;
    if (tid == 0) qh = 0;
    __syncthreads();

    // per-row min + argmin (5 warps over 50 rows); u init
    for (int row = wid; row < NT; row += NWARP) {
        const float* rp = lbase + row*NQ;
        float bv = INF; int bi = NQ;
        for (int j = lane; j < NQ; j += 32) {
            float v = rp[j];
            if (v < bv) { bv = v; bi = j; }
        }
        int fi = warp_argmin(bv, bi);
        if (lane == 0) { rmin[row] = bv; ramin[row] = fi; u[row] = bv; }
    }
    __syncthreads();

    // warp 0: greedy conflict-free assignment + freelist
    if (tid < 32) {
        if (lane == 0) {
            #pragma unroll 1
            for (int i = 0; i < NT; i++) {
                int j = ramin[i];
                if (vo_o(vown[j]) == -1) { vown[j] = packvo(0.f, i); col4row[i] = j; }
            }
        }
        __syncwarp();
        int nfree = 0;
        #pragma unroll
        for (int base = 0; base < NT; base += 32) {
            int t = base + lane;
            bool fr = (t < NT) && (col4row[t] == -1);
            unsigned m = __ballot_sync(0xffffffffu, fr);
            int pos = nfree + __popc(m & ((1u << lane) - 1u));
            if (fr) freelist[pos] = t;
            nfree += __popc(m);
        }
        if (lane == 0) nfree_sh = nfree;
    }
    __syncthreads();

    // ---- PARALLEL JV augmenting row reduction: all 5 warps ----
    {
        const int nfree = nfree_sh;
        int budget = SCANBUDGET;
        for (;;) {
            int idx = 0;
            if (lane == 0) idx = atomicAdd(&qh, 1);
            idx = __shfl_sync(0xffffffffu, idx, 0);
            if (idx >= nfree || budget <= 0) break;
            int i = freelist[idx];

            bool alive = true;
            while (alive && budget > 0) {
                budget--;
                const float* lrow = lbase + i*NQ;
                float l1 = INF, l2 = INF; int b1 = NQ; ull p1 = 0;
                #pragma unroll
                for (int k = 0; k < NK; k++) {
                    int j = k*32 + lane;
                    if (j < NQ) {
                        ull pv = vvown[j];
                        float w = lrow[j] - vo_v(pv);
                        if (w < l1) { l2 = l1; l1 = w; b1 = j; p1 = pv; }
                        else if (w < l2) l2 = w;
                    }
                }
                unsigned m1 = __reduce_min_sync(0xffffffffu, fmap(l1));
                unsigned bal = __ballot_sync(0xffffffffu, fmap(l1) == m1);
                int win = __ffs(bal) - 1;
                int j1  = __shfl_sync(0xffffffffu, b1, win);
                ull p64 = __shfl_sync(0xffffffffu, p1, win);
                float u1 = finv(m1);
                float cand = (lane == win) ? l2 : l1;
                float u2 = finv(__reduce_min_sync(0xffffffffu, fmap(cand)));

                int owner1 = vo_o(p64);
                if (!(u1 < u2) && owner1 != -1) { alive = false; break; }

                int ok = 0;
                if (lane == win) {
                    float vnew = vo_v(p64) - (u2 - u1);
                    ok = (atomicCAS(&vown[j1], p64, packvo(vnew, i)) == p64);
                }
                ok = __shfl_sync(0xffffffffu, ok, win);
                if (!ok) continue;

                if (lane == win) {
                    u[i] = u2;
                    col4row[i] = j1;
                    if (owner1 != -1) col4row[owner1] = -1;
                }
                __syncwarp();
                if (owner1 == -1) alive = false;
                else i = owner1;
            }
        }
    }
    __syncthreads();
    if (tid >= 32) return;                 // warp 0 finishes alone

    // extract v / row4col for Dijkstra
    float vloc[NK];
    #pragma unroll
    for (int k = 0; k < NK; k++) {
        int j = k*32 + lane;
        vloc[k] = (j < NQ) ? vo_v(vown[j]) : 0.f;
    }
    for (int j = lane; j < NQ; j += 32) row4col[j] = vo_o(vown[j]);
    __syncwarp();

    float shortest[NK];

    // shortest augmenting path for whatever remains (exact backstop)
    for (int curRow = 0; curRow < NT; curRow++) {
        if (col4row[curRow] != -1) continue;

        #pragma unroll
        for (int k = 0; k < NK; k++) shortest[k] = INF;
        unsigned sc = 0;
        int   i  = curRow;
        float mv = 0.f;
        int   nsteps = 0;
        int   sink = -1;

        while (true) {
            const float base = mv - u[i];
            const float* lrow = lbase + i*NQ;

            float bv = INF; int bi = NQ;
            #pragma unroll
            for (int k = 0; k < NK; k++) {
                int j = k*32 + lane;
                if (j < NQ && !((sc >> k) & 1u)) {
                    float rr = base + lrow[j] - vloc[k];
                    if (rr < shortest[k]) { shortest[k] = rr; path[j] = i; }
                    if (shortest[k] < bv) { bv = shortest[k]; bi = j; }
                }
            }

            int fi = warp_argmin(bv, bi);
            mv = bv;

            if (lane == (fi & 31)) sc |= 1u << (fi >> 5);
            if (lane == 0) { selj[nsteps] = fi; selv[nsteps] = mv; }
            nsteps++;

            int r4 = row4col[fi];
            if (r4 == -1) { sink = fi; break; }
            i = r4;
        }

        __syncwarp();

        if (lane == 0) u[curRow] += mv;
        for (int s = lane; s < nsteps - 1; s += 32) {
            int i2 = row4col[selj[s]];
            u[i2] += mv - selv[s];
        }
        for (int s = 0; s < nsteps; s++) {
            int j = selj[s];
            if ((j & 31) == lane) vloc[j >> 5] -= mv - selv[s];
        }
        __syncwarp();

        if (lane == 0) {
            int j = sink;
            while (true) {
                int i2 = path[j];
                row4col[j] = i2;
                int nj = col4row[i2];
                col4row[i2] = j;
                j = nj;
                if (i2 == curRow) break;
            }
        }
        __syncwarp();
    }

    // emit indices sorted by query (rank counting)
    for (int t = lane; t < NT; t += 32) {
        int q = col4row[t];
        int rank = 0;
        #pragma unroll
        for (int t2 = 0; t2 < NT; t2++) rank += (col4row[t2] < q) ? 1 : 0;
        size_t base = (size_t)NROW * NCOL + (size_t)b * 2 * NT;
        out[base + rank]      = (float)q;
        out[base + NT + rank] = (float)t;
    }
}

// ---------------------------------------------------------
extern "C" void kernel_launch(void* const* d_in, const int* in_sizes, int n_in,
                              void* d_out, int out_size) {
    const float* pred_kp   = (const float*)d_in[0];  // (16,300,51)
    const float* pred_box  = (const float*)d_in[1];  // (16,300,6)
    const float* tgt_box   = (const float*)d_in[2];  // (16,50,6)
    const float* tgt_kp    = (const float*)d_in[3];  // (16,50,51)
    float* out = (float*)d_out;

    diag_kernel<<<DIAG_BLKS, 256>>>(pred_kp, pred_box, tgt_kp, tgt_box);
    fused_kernel<<<BS + GBX*GBY, TPB, DYN_BYTES>>>(pred_kp, pred_box, tgt_kp, tgt_box, out);
}

// round 13
// speedup vs baseline: 2.1291x; 1.0052x over previous
#include <cuda_runtime.h>
#include <cuda_bf16.h>

#define BS 16
#define NQ 300
#define NT 50
#define KP3 51          // 17 keypoints * 3
#define KPP 52          // padded (float4/ull2-friendly)
#define NCOL (BS*NT)    // 800
#define NROW (BS*NQ)    // 4800
#define NK 10           // columns per lane in LAP (10*32 >= 300)
#define CBLK 160        // cols per cost block == blockDim
#define TPB  160
#define NWARP (TPB/32)  // 5
#define RBLK 32         // rows per cost block
#define GBX  (NCOL/CBLK)   // 5
#define GBY  (NROW/RBLK)   // 150
#define ACH  80         // phase-A chunk (columns)
#define TGRP 10         // targets per diag block
#define DIAG_BLKS (BS*(NT/TGRP))  // 80
#define SCANBUDGET 160  // per-warp JV scan budget

// dynamic smem (floats): cost staging only
// phase A chunk: ACH*(KP3+6) = 4560 ; phase B: RBLK*(KPP+6) = 1856
#define DYN_FLOATS 4560
#define DYN_BYTES (DYN_FLOATS*4)   // 18240 B -> 4 CTAs/SM fits easily

typedef unsigned long long ull;

__device__ float g_lap[BS*NT*NQ];   // per-batch transposed diag cost [b][t][q]

#define ADD_F32X2(out, a, b) \
    asm("add.rn.f32x2 %0, %1, %2;" : "=l"(out) : "l"(a), "l"(b))

__device__ __forceinline__ float frcp(float x) {
    float r;
    asm("rcp.approx.f32 %0, %1;" : "=f"(r) : "f"(x));
    return r;
}
__device__ __forceinline__ unsigned fmap(float f) {
    unsigned u = __float_as_uint(f);
    return (u & 0x80000000u) ? ~u : (u | 0x80000000u);
}
__device__ __forceinline__ float finv(unsigned u) {
    return __uint_as_float((u & 0x80000000u) ? (u & 0x7FFFFFFFu) : ~u);
}
__device__ __forceinline__ int warp_argmin(float& bv, int bi) {
    unsigned bu  = fmap(bv);
    unsigned mvu = __reduce_min_sync(0xffffffffu, bu);
    unsigned bal = __ballot_sync(0xffffffffu, bu == mvu);
    int src = __ffs(bal) - 1;
    bv = finv(mvu);
    return __shfl_sync(0xffffffffu, bi, src);
}
__device__ __forceinline__ ull packvo(float v, int owner) {
    return ((ull)__float_as_uint(v) << 32) | (unsigned)owner;
}
__device__ __forceinline__ float vo_v(ull p) { return __uint_as_float((unsigned)(p >> 32)); }
__device__ __forceinline__ int   vo_o(ull p) { return (int)(unsigned)(p & 0xffffffffu); }

// ---------------------------------------------------------
// Kernel 1: diagonal cost blocks -> g_lap. 80 blocks x 256 thr.
// ---------------------------------------------------------
__global__ void __launch_bounds__(256) diag_kernel(const float* __restrict__ pkp,
                                                   const float* __restrict__ pbox,
                                                   const float* __restrict__ tkp,
                                                   const float* __restrict__ tbox) {
    __shared__ __align__(16) float sdk[TGRP][KPP];
    __shared__ float stmn[TGRP][3], stmx[TGRP][3], stvol[TGRP];
    const int tid = threadIdx.x;
    const int b   = blockIdx.x / (NT/TGRP);
    const int tg  = blockIdx.x % (NT/TGRP);

    if (tid < TGRP) {
        int g = b*NT + tg*TGRP + tid;
        float sz[3], rsz[3];
        #pragma unroll
        for (int d = 0; d < 3; d++) {
            float ctr = tbox[g*6 + d];
            sz[d]     = tbox[g*6 + 3 + d];
            rsz[d]    = frcp(sz[d]);
            stmn[tid][d] = ctr - 0.5f*sz[d];
            stmx[tid][d] = ctr + 0.5f*sz[d];
        }
        stvol[tid] = sz[0]*sz[1]*sz[2];
        #pragma unroll
        for (int k = 0; k < KP3; k++) {
            int d = k - (k/3)*3;
            sdk[tid][k] = (tkp[(size_t)g*KP3 + k] - stmn[tid][d]) * rsz[d];
        }
        sdk[tid][KP3] = 0.f;
    }
    __syncthreads();

    for (int q = tid; q < NQ; q += 256) {
        float4 pk4[KPP/4];
        {
            float tmpk[KPP];
            const float* pr = pkp + (size_t)(b*NQ + q)*KP3;
            #pragma unroll
            for (int k = 0; k < KP3; k++) tmpk[k] = pr[k];
            tmpk[KP3] = 0.f;
            #pragma unroll
            for (int k4 = 0; k4 < KPP/4; k4++)
                pk4[k4] = make_float4(tmpk[4*k4], tmpk[4*k4+1], tmpk[4*k4+2], tmpk[4*k4+3]);
        }
        float pmn[3], pmx[3];
        #pragma unroll
        for (int d = 0; d < 3; d++) {
            float cc = pbox[(size_t)(b*NQ + q)*6 + d];
            float ss = pbox[(size_t)(b*NQ + q)*6 + 3 + d];
            pmn[d] = cc - 0.5f*ss; pmx[d] = cc + 0.5f*ss;
        }
        float vol1 = (pmx[0]-pmn[0])*(pmx[1]-pmn[1])*(pmx[2]-pmn[2]);

        #pragma unroll 2
        for (int tr = 0; tr < TGRP; tr++) {
            const float4* srow = (const float4*)sdk[tr];
            float s0 = 0.f, s1 = 0.f, s2 = 0.f, s3 = 0.f;
            #pragma unroll
            for (int k4 = 0; k4 < KPP/4; k4++) {
                float4 d4 = srow[k4];
                s0 += fabsf(pk4[k4].x - d4.x);
                s1 += fabsf(pk4[k4].y - d4.y);
                s2 += fabsf(pk4[k4].z - d4.z);
                s3 += fabsf(pk4[k4].w - d4.w);
            }
            float s = (s0 + s1) + (s2 + s3);
            float inter = 1.f, evol = 1.f;
            #pragma unroll
            for (int d = 0; d < 3; d++) {
                float tn = stmn[tr][d], tx = stmx[tr][d];
                inter *= fmaxf(fminf(pmx[d], tx) - fmaxf(pmn[d], tn), 0.f);
                evol  *= fmaxf(fmaxf(pmx[d], tx) - fminf(pmn[d], tn), 0.f);
            }
            float uni = vol1 + stvol[tr] - inter;
            float giou = inter*frcp(uni) - (evol - uni)*frcp(evol);
            g_lap[(size_t)(b*NT + tg*TGRP + tr)*NQ + q] = s - giou;
        }
    }
}

// ---------------------------------------------------------
// Kernel 2: fused, 766 blocks @ 4 CTAs/SM.
// blocks [0,16): LAP (reads g_lap via L1).  blocks [16,766): C matrix.
// ---------------------------------------------------------
__global__ void __launch_bounds__(TPB, 4) fused_kernel(const float* __restrict__ pkp,
                                                       const float* __restrict__ pbox,
                                                       const float* __restrict__ tkp,
                                                       const float* __restrict__ tbox,
                                                       float* __restrict__ out) {
    extern __shared__ __align__(16) float dsm[];
    const int tid = threadIdx.x;

    if (blockIdx.x >= BS) {
        // ================== COST-MATRIX PATH ==================
        float* buf = dsm;
        const int cb = blockIdx.x - BS;
        const int c0 = (cb % GBX) * CBLK;
        const int r0 = (cb / GBX) * RBLK;
        const int c  = c0 + tid;

        ull  ndk[KPP/2];
        float tmn[3], tmx[3], tvol = 0.f;

        // phase A: two chunks of 80 target columns -> registers
        #pragma unroll 1
        for (int ch = 0; ch < 2; ch++) {
            const int cc0 = ch * ACH;
            for (int i = tid; i < ACH*KP3; i += TPB) buf[i] = tkp[(size_t)(c0+cc0)*KP3 + i];
            for (int i = tid; i < ACH*6;  i += TPB) buf[ACH*KP3 + i] = tbox[(size_t)(c0+cc0)*6 + i];
            __syncthreads();
            if (tid >= cc0 && tid < cc0 + ACH) {
                const int lt = tid - cc0;
                float sz[3], rsz[3];
                #pragma unroll
                for (int d = 0; d < 3; d++) {
                    float ctr = buf[ACH*KP3 + lt*6 + d];
                    sz[d]     = buf[ACH*KP3 + lt*6 + 3 + d];
                    rsz[d]    = frcp(sz[d]);
                    tmn[d] = ctr - 0.5f*sz[d];
                    tmx[d] = ctr + 0.5f*sz[d];
                }
                tvol = sz[0]*sz[1]*sz[2];
                float dk[KPP];
                #pragma unroll
                for (int k = 0; k < KP3; k++) {
                    int d = k - (k/3)*3;
                    dk[k] = (buf[lt*KP3 + k] - tmn[d]) * rsz[d];
                }
                dk[KP3] = 0.f;
                #pragma unroll
                for (int k2 = 0; k2 < KPP/2; k2++) {
                    float lo = -dk[2*k2], hi = -dk[2*k2+1];
                    asm("mov.b64 %0, {%1, %2};" : "=l"(ndk[k2]) : "f"(lo), "f"(hi));
                }
            }
            __syncthreads();
        }

        // phase B: pred rows padded to 52 + boxes
        for (int i = tid; i < RBLK*KPP; i += TPB) {
            int r = i / KPP, k = i - r*KPP;
            buf[i] = (k < KP3) ? pkp[(size_t)(r0+r)*KP3 + k] : 0.f;
        }
        for (int i = tid; i < RBLK*6; i += TPB) buf[RBLK*KPP + i] = pbox[(size_t)r0*6 + i];
        __syncthreads();

        const ull AMASK = 0x7FFFFFFF7FFFFFFFULL;
        #pragma unroll 2
        for (int r = 0; r < RBLK; r++) {
            const ulonglong2* prow = (const ulonglong2*)&buf[r*KPP];
            ull sacc[4] = {0, 0, 0, 0};
            #pragma unroll
            for (int k4 = 0; k4 < KPP/4; k4++) {
                ulonglong2 p = prow[k4];
                ull d0; ADD_F32X2(d0, p.x, ndk[2*k4]);
                d0 &= AMASK;
                ADD_F32X2(sacc[(2*k4)&3], sacc[(2*k4)&3], d0);
                ull d1; ADD_F32X2(d1, p.y, ndk[2*k4+1]);
                d1 &= AMASK;
                ADD_F32X2(sacc[(2*k4+1)&3], sacc[(2*k4+1)&3], d1);
            }
            ull sAB; ADD_F32X2(sAB, sacc[0], sacc[1]);
            ull sCD; ADD_F32X2(sCD, sacc[2], sacc[3]);
            ull st;  ADD_F32X2(st, sAB, sCD);
            float slo, shi;
            asm("mov.b64 {%0, %1}, %2;" : "=f"(slo), "=f"(shi) : "l"(st));
            float s = slo + shi;

            float pmn[3], pmx[3];
            #pragma unroll
            for (int d = 0; d < 3; d++) {
                float cc = buf[RBLK*KPP + r*6 + d];
                float ss = buf[RBLK*KPP + r*6 + 3 + d];
                pmn[d] = cc - 0.5f*ss; pmx[d] = cc + 0.5f*ss;
            }
            float vol1 = (pmx[0]-pmn[0])*(pmx[1]-pmn[1])*(pmx[2]-pmn[2]);
            float inter = 1.f, evol = 1.f;
            #pragma unroll
            for (int d = 0; d < 3; d++) {
                inter *= fmaxf(fminf(pmx[d], tmx[d]) - fmaxf(pmn[d], tmn[d]), 0.f);
                evol  *= fmaxf(fmaxf(pmx[d], tmx[d]) - fminf(pmn[d], tmn[d]), 0.f);
            }
            float uni = vol1 + tvol - inter;
            float giou = inter*frcp(uni) - (evol - uni)*frcp(evol);
            out[(size_t)(r0+r)*NCOL + c] = s - giou;
        }
        return;
    }

    // ================== LAP PATH (blocks 0..15) ==================
    // cost rows read directly from g_lap (L1-resident after first pass)
    const int b    = blockIdx.x;
    const int lane = tid & 31;
    const int wid  = tid >> 5;
    const float INF = 3.0e38f;
    const float* lbase = &g_lap[(size_t)b*NT*NQ];

    __shared__ ull   vown[NQ];          // packed (v, owner)
    __shared__ float u[NT];
    __shared__ float rmin[NT];
    __shared__ int   ramin[NT];
    __shared__ int   path[NQ];
    __shared__ int   row4col[NQ];
    __shared__ int   col4row[NT];
    __shared__ int   selj[NQ + 2];
    __shared__ float selv[NQ + 2];
    __shared__ int   freelist[NT];
    __shared__ int   qh, nfree_sh;
    volatile ull* vvown = (volatile ull*)vown;

    for (int j = tid; j < NQ; j += TPB) vown[j] = packvo(0.f, -1);
    if (tid < NT) col4row[tid] = -1;
    if (tid == 0) qh = 0;
    __syncthreads();

    // per-row min + argmin (5 warps over 50 rows); u init
    for (int row = wid; row < NT; row += NWARP) {
        const float* rp = lbase + row*NQ;
        float bv = INF; int bi = NQ;
        for (int j = lane; j < NQ; j += 32) {
            float v = rp[j];
            if (v < bv) { bv = v; bi = j; }
        }
        int fi = warp_argmin(bv, bi);
        if (lane == 0) { rmin[row] = bv; ramin[row] = fi; u[row] = bv; }
    }
    __syncthreads();

    // warp 0: greedy conflict-free assignment + freelist
    if (tid < 32) {
        if (lane == 0) {
            #pragma unroll 1
            for (int i = 0; i < NT; i++) {
                int j = ramin[i];
                if (vo_o(vown[j]) == -1) { vown[j] = packvo(0.f, i); col4row[i] = j; }
            }
        }
        __syncwarp();
        int nfree = 0;
        #pragma unroll
        for (int base = 0; base < NT; base += 32) {
            int t = base + lane;
            bool fr = (t < NT) && (col4row[t] == -1);
            unsigned m = __ballot_sync(0xffffffffu, fr);
            int pos = nfree + __popc(m & ((1u << lane) - 1u));
            if (fr) freelist[pos] = t;
            nfree += __popc(m);
        }
        if (lane == 0) nfree_sh = nfree;
    }
    __syncthreads();

    // ---- PARALLEL JV augmenting row reduction: all 5 warps ----
    {
        const int nfree = nfree_sh;
        int budget = SCANBUDGET;
        for (;;) {
            int idx = 0;
            if (lane == 0) idx = atomicAdd(&qh, 1);
            idx = __shfl_sync(0xffffffffu, idx, 0);
            if (idx >= nfree || budget <= 0) break;
            int i = freelist[idx];

            bool alive = true;
            while (alive && budget > 0) {
                budget--;
                const float* lrow = lbase + i*NQ;
                float l1 = INF, l2 = INF; int b1 = NQ; ull p1 = 0;
                #pragma unroll
                for (int k = 0; k < NK; k++) {
                    int j = k*32 + lane;
                    if (j < NQ) {
                        ull pv = vvown[j];
                        float w = lrow[j] - vo_v(pv);
                        if (w < l1) { l2 = l1; l1 = w; b1 = j; p1 = pv; }
                        else if (w < l2) l2 = w;
                    }
                }
                unsigned m1 = __reduce_min_sync(0xffffffffu, fmap(l1));
                unsigned bal = __ballot_sync(0xffffffffu, fmap(l1) == m1);
                int win = __ffs(bal) - 1;
                int j1  = __shfl_sync(0xffffffffu, b1, win);
                ull p64 = __shfl_sync(0xffffffffu, p1, win);
                float u1 = finv(m1);
                float cand = (lane == win) ? l2 : l1;
                float u2 = finv(__reduce_min_sync(0xffffffffu, fmap(cand)));

                int owner1 = vo_o(p64);
                if (!(u1 < u2) && owner1 != -1) { alive = false; break; }

                int ok = 0;
                if (lane == win) {
                    float vnew = vo_v(p64) - (u2 - u1);
                    ok = (atomicCAS(&vown[j1], p64, packvo(vnew, i)) == p64);
                }
                ok = __shfl_sync(0xffffffffu, ok, win);
                if (!ok) continue;

                if (lane == win) {
                    u[i] = u2;
                    col4row[i] = j1;
                    if (owner1 != -1) col4row[owner1] = -1;
                }
                __syncwarp();
                if (owner1 == -1) alive = false;
                else i = owner1;
            }
        }
    }
    __syncthreads();
    if (tid >= 32) return;                 // warp 0 finishes alone

    // extract v / row4col for Dijkstra
    float vloc[NK];
    #pragma unroll
    for (int k = 0; k < NK; k++) {
        int j = k*32 + lane;
        vloc[k] = (j < NQ) ? vo_v(vown[j]) : 0.f;
    }
    for (int j = lane; j < NQ; j += 32) row4col[j] = vo_o(vown[j]);
    __syncwarp();

    float shortest[NK];

    // shortest augmenting path for whatever remains (exact backstop)
    for (int curRow = 0; curRow < NT; curRow++) {
        if (col4row[curRow] != -1) continue;

        #pragma unroll
        for (int k = 0; k < NK; k++) shortest[k] = INF;
        unsigned sc = 0;
        int   i  = curRow;
        float mv = 0.f;
        int   nsteps = 0;
        int   sink = -1;

        while (true) {
            const float base = mv - u[i];
            const float* lrow = lbase + i*NQ;

            float bv = INF; int bi = NQ;
            #pragma unroll
            for (int k = 0; k < NK; k++) {
                int j = k*32 + lane;
                if (j < NQ && !((sc >> k) & 1u)) {
                    float rr = base + lrow[j] - vloc[k];
                    if (rr < shortest[k]) { shortest[k] = rr; path[j] = i; }
                    if (shortest[k] < bv) { bv = shortest[k]; bi = j; }
                }
            }

            int fi = warp_argmin(bv, bi);
            mv = bv;

            if (lane == (fi & 31)) sc |= 1u << (fi >> 5);
            if (lane == 0) { selj[nsteps] = fi; selv[nsteps] = mv; }
            nsteps++;

            int r4 = row4col[fi];
            if (r4 == -1) { sink = fi; break; }
            i = r4;
        }

        __syncwarp();

        if (lane == 0) u[curRow] += mv;
        for (int s = lane; s < nsteps - 1; s += 32) {
            int i2 = row4col[selj[s]];
            u[i2] += mv - selv[s];
        }
        for (int s = 0; s < nsteps; s++) {
            int j = selj[s];
            if ((j & 31) == lane) vloc[j >> 5] -= mv - selv[s];
        }
        __syncwarp();

        if (lane == 0) {
            int j = sink;
            while (true) {
                int i2 = path[j];
                row4col[j] = i2;
                int nj = col4row[i2];
                col4row[i2] = j;
                j = nj;
                if (i2 == curRow) break;
            }
        }
        __syncwarp();
    }

    // emit indices sorted by query (rank counting)
    for (int t = lane; t < NT; t += 32) {
        int q = col4row[t];
        int rank = 0;
        #pragma unroll
        for (int t2 = 0; t2 < NT; t2++) rank += (col4row[t2] < q) ? 1 : 0;
        size_t base = (size_t)NROW * NCOL + (size_t)b * 2 * NT;
        out[base + rank]      = (float)q;
        out[base + NT + rank] = (float)t;
    }
}

// ---------------------------------------------------------
extern "C" void kernel_launch(void* const* d_in, const int* in_sizes, int n_in,
                              void* d_out, int out_size) {
    const float* pred_kp   = (const float*)d_in[0];  // (16,300,51)
    const float* pred_box  = (const float*)d_in[1];  // (16,300,6)
    const float* tgt_box   = (const float*)d_in[2];  // (16,50,6)
    const float* tgt_kp    = (const float*)d_in[3];  // (16,50,51)
    float* out = (float*)d_out;

    diag_kernel<<<DIAG_BLKS, 256>>>(pred_kp, pred_box, tgt_kp, tgt_box);
    fused_kernel<<<BS + GBX*GBY, TPB, DYN_BYTES>>>(pred_kp, pred_box, tgt_kp, tgt_box, out);
}

// round 15
// speedup vs baseline: 2.2879x; 1.0746x over previous
#include <cuda_runtime.h>
#include <cuda_bf16.h>

#define BS 16
#define NQ 300
#define NT 50
#define KP3 51          // 17 keypoints * 3
#define KPP 52          // padded (float4/ull2-friendly)
#define NCOL (BS*NT)    // 800
#define NROW (BS*NQ)    // 4800
#define NK 10           // columns per lane in LAP (10*32 >= 300)
#define CBLK 160        // cols per cost block == blockDim
#define TPB  160
#define NWARP (TPB/32)  // 5
#define GBX  (NCOL/CBLK)   // 5 column tiles
#define RSLICES 115     // row slices per column tile (5*115+16 = 591 <= 592 slots)
#define RMAX 42         // max rows per slice (ceil(4800/115))
#define ACH  80         // phase-A chunk (columns)
#define TGRP 10         // targets per diag block
#define DIAG_BLKS (BS*(NT/TGRP))  // 80
#define SCANBUDGET 160  // per-warp JV scan budget

// dynamic smem (floats): phase A chunk ACH*(KP3+6)=4560 ; phase B RMAX*(KPP+6)=2436
#define DYN_FLOATS 4560
#define DYN_BYTES (DYN_FLOATS*4)   // 18240 B -> 4 CTAs/SM

typedef unsigned long long ull;

__device__ float g_lap[BS*NT*NQ];   // per-batch transposed diag cost [b][t][q]

#define ADD_F32X2(out, a, b) \
    asm("add.rn.f32x2 %0, %1, %2;" : "=l"(out) : "l"(a), "l"(b))

__device__ __forceinline__ float frcp(float x) {
    float r;
    asm("rcp.approx.f32 %0, %1;" : "=f"(r) : "f"(x));
    return r;
}
__device__ __forceinline__ unsigned fmap(float f) {
    unsigned u = __float_as_uint(f);
    return (u & 0x80000000u) ? ~u : (u | 0x80000000u);
}
__device__ __forceinline__ float finv(unsigned u) {
    return __uint_as_float((u & 0x80000000u) ? (u & 0x7FFFFFFFu) : ~u);
}
__device__ __forceinline__ int warp_argmin(float& bv, int bi) {
    unsigned bu  = fmap(bv);
    unsigned mvu = __reduce_min_sync(0xffffffffu, bu);
    unsigned bal = __ballot_sync(0xffffffffu, bu == mvu);
    int src = __ffs(bal) - 1;
    bv = finv(mvu);
    return __shfl_sync(0xffffffffu, bi, src);
}
__device__ __forceinline__ ull packvo(float v, int owner) {
    return ((ull)__float_as_uint(v) << 32) | (unsigned)owner;
}
__device__ __forceinline__ float vo_v(ull p) { return __uint_as_float((unsigned)(p >> 32)); }
__device__ __forceinline__ int   vo_o(ull p) { return (int)(unsigned)(p & 0xffffffffu); }

// ---------------------------------------------------------
// Kernel 1: diagonal cost blocks -> g_lap. 80 blocks x 256 thr.
// ---------------------------------------------------------
__global__ void __launch_bounds__(256) diag_kernel(const float* __restrict__ pkp,
                                                   const float* __restrict__ pbox,
                                                   const float* __restrict__ tkp,
                                                   const float* __restrict__ tbox) {
    __shared__ __align__(16) float sdk[TGRP][KPP];
    __shared__ float stmn[TGRP][3], stmx[TGRP][3], stvol[TGRP];
    const int tid = threadIdx.x;
    const int b   = blockIdx.x / (NT/TGRP);
    const int tg  = blockIdx.x % (NT/TGRP);

    if (tid < TGRP) {
        int g = b*NT + tg*TGRP + tid;
        float sz[3], rsz[3];
        #pragma unroll
        for (int d = 0; d < 3; d++) {
            float ctr = tbox[g*6 + d];
            sz[d]     = tbox[g*6 + 3 + d];
            rsz[d]    = frcp(sz[d]);
            stmn[tid][d] = ctr - 0.5f*sz[d];
            stmx[tid][d] = ctr + 0.5f*sz[d];
        }
        stvol[tid] = sz[0]*sz[1]*sz[2];
        #pragma unroll
        for (int k = 0; k < KP3; k++) {
            int d = k - (k/3)*3;
            sdk[tid][k] = (tkp[(size_t)g*KP3 + k] - stmn[tid][d]) * rsz[d];
        }
        sdk[tid][KP3] = 0.f;
    }
    __syncthreads();

    for (int q = tid; q < NQ; q += 256) {
        float4 pk4[KPP/4];
        {
            float tmpk[KPP];
            const float* pr = pkp + (size_t)(b*NQ + q)*KP3;
            #pragma unroll
            for (int k = 0; k < KP3; k++) tmpk[k] = pr[k];
            tmpk[KP3] = 0.f;
            #pragma unroll
            for (int k4 = 0; k4 < KPP/4; k4++)
                pk4[k4] = make_float4(tmpk[4*k4], tmpk[4*k4+1], tmpk[4*k4+2], tmpk[4*k4+3]);
        }
        float pmn[3], pmx[3];
        #pragma unroll
        for (int d = 0; d < 3; d++) {
            float cc = pbox[(size_t)(b*NQ + q)*6 + d];
            float ss = pbox[(size_t)(b*NQ + q)*6 + 3 + d];
            pmn[d] = cc - 0.5f*ss; pmx[d] = cc + 0.5f*ss;
        }
        float vol1 = (pmx[0]-pmn[0])*(pmx[1]-pmn[1])*(pmx[2]-pmn[2]);

        #pragma unroll 2
        for (int tr = 0; tr < TGRP; tr++) {
            const float4* srow = (const float4*)sdk[tr];
            float s0 = 0.f, s1 = 0.f, s2 = 0.f, s3 = 0.f;
            #pragma unroll
            for (int k4 = 0; k4 < KPP/4; k4++) {
                float4 d4 = srow[k4];
                s0 += fabsf(pk4[k4].x - d4.x);
                s1 += fabsf(pk4[k4].y - d4.y);
                s2 += fabsf(pk4[k4].z - d4.z);
                s3 += fabsf(pk4[k4].w - d4.w);
            }
            float s = (s0 + s1) + (s2 + s3);
            float inter = 1.f, evol = 1.f;
            #pragma unroll
            for (int d = 0; d < 3; d++) {
                float tn = stmn[tr][d], tx = stmx[tr][d];
                inter *= fmaxf(fminf(pmx[d], tx) - fmaxf(pmn[d], tn), 0.f);
                evol  *= fmaxf(fmaxf(pmx[d], tx) - fminf(pmn[d], tn), 0.f);
            }
            float uni = vol1 + stvol[tr] - inter;
            float giou = inter*frcp(uni) - (evol - uni)*frcp(evol);
            g_lap[(size_t)(b*NT + tg*TGRP + tr)*NQ + q] = s - giou;
        }
    }
}

// ---------------------------------------------------------
// Kernel 2: fused, SINGLE WAVE (591 blocks @ 4 CTAs/SM = 592 slots).
// blocks [0,16): LAP.  blocks [16,591): C matrix, one col-tile x ~42-row slice.
// ---------------------------------------------------------
__global__ void __launch_bounds__(TPB, 4) fused_kernel(const float* __restrict__ pkp,
                                                       const float* __restrict__ pbox,
                                                       const float* __restrict__ tkp,
                                                       const float* __restrict__ tbox,
                                                       float* __restrict__ out) {
    extern __shared__ __align__(16) float dsm[];
    const int tid = threadIdx.x;

    if (blockIdx.x >= BS) {
        // ================== COST-MATRIX PATH ==================
        float* buf = dsm;
        const int cb   = blockIdx.x - BS;        // 0..574
        const int ct   = cb / RSLICES;           // column tile 0..4
        const int ridx = cb - ct * RSLICES;      // row slice 0..114
        const int c0 = ct * CBLK;
        const int r0 = (ridx * NROW) / RSLICES;
        const int r1 = ((ridx + 1) * NROW) / RSLICES;
        const int nr = r1 - r0;                  // 41 or 42
        const int c  = c0 + tid;

        ull  ndk[KPP/2];
        float tmn[3], tmx[3], tvol = 0.f;

        // phase A: two chunks of 80 target columns -> registers
        #pragma unroll 1
        for (int ch = 0; ch < 2; ch++) {
            const int cc0 = ch * ACH;
            for (int i = tid; i < ACH*KP3; i += TPB) buf[i] = tkp[(size_t)(c0+cc0)*KP3 + i];
            for (int i = tid; i < ACH*6;  i += TPB) buf[ACH*KP3 + i] = tbox[(size_t)(c0+cc0)*6 + i];
            __syncthreads();
            if (tid >= cc0 && tid < cc0 + ACH) {
                const int lt = tid - cc0;
                float sz[3], rsz[3];
                #pragma unroll
                for (int d = 0; d < 3; d++) {
                    float ctr = buf[ACH*KP3 + lt*6 + d];
                    sz[d]     = buf[ACH*KP3 + lt*6 + 3 + d];
                    rsz[d]    = frcp(sz[d]);
                    tmn[d] = ctr - 0.5f*sz[d];
                    tmx[d] = ctr + 0.5f*sz[d];
                }
                tvol = sz[0]*sz[1]*sz[2];
                float dk[KPP];
                #pragma unroll
                for (int k = 0; k < KP3; k++) {
                    int d = k - (k/3)*3;
                    dk[k] = (buf[lt*KP3 + k] - tmn[d]) * rsz[d];
                }
                dk[KP3] = 0.f;
                #pragma unroll
                for (int k2 = 0; k2 < KPP/2; k2++) {
                    float lo = -dk[2*k2], hi = -dk[2*k2+1];
                    asm("mov.b64 %0, {%1, %2};" : "=l"(ndk[k2]) : "f"(lo), "f"(hi));
                }
            }
            __syncthreads();
        }

        // phase B: nr pred rows padded to 52 + boxes
        for (int i = tid; i < nr*KPP; i += TPB) {
            int r = i / KPP, k = i - r*KPP;
            buf[i] = (k < KP3) ? pkp[(size_t)(r0+r)*KP3 + k] : 0.f;
        }
        for (int i = tid; i < nr*6; i += TPB) buf[RMAX*KPP + i] = pbox[(size_t)r0*6 + i];
        __syncthreads();

        const ull AMASK = 0x7FFFFFFF7FFFFFFFULL;
        #pragma unroll 2
        for (int r = 0; r < nr; r++) {
            const ulonglong2* prow = (const ulonglong2*)&buf[r*KPP];
            ull sacc[4] = {0, 0, 0, 0};
            #pragma unroll
            for (int k4 = 0; k4 < KPP/4; k4++) {
                ulonglong2 p = prow[k4];
                ull d0; ADD_F32X2(d0, p.x, ndk[2*k4]);
                d0 &= AMASK;
                ADD_F32X2(sacc[(2*k4)&3], sacc[(2*k4)&3], d0);
                ull d1; ADD_F32X2(d1, p.y, ndk[2*k4+1]);
                d1 &= AMASK;
                ADD_F32X2(sacc[(2*k4+1)&3], sacc[(2*k4+1)&3], d1);
            }
            ull sAB; ADD_F32X2(sAB, sacc[0], sacc[1]);
            ull sCD; ADD_F32X2(sCD, sacc[2], sacc[3]);
            ull st;  ADD_F32X2(st, sAB, sCD);
            float slo, shi;
            asm("mov.b64 {%0, %1}, %2;" : "=f"(slo), "=f"(shi) : "l"(st));
            float s = slo + shi;

            float pmn[3], pmx[3];
            #pragma unroll
            for (int d = 0; d < 3; d++) {
                float cc = buf[RMAX*KPP + r*6 + d];
                float ss = buf[RMAX*KPP + r*6 + 3 + d];
                pmn[d] = cc - 0.5f*ss; pmx[d] = cc + 0.5f*ss;
            }
            float vol1 = (pmx[0]-pmn[0])*(pmx[1]-pmn[1])*(pmx[2]-pmn[2]);
            float inter = 1.f, evol = 1.f;
            #pragma unroll
            for (int d = 0; d < 3; d++) {
                inter *= fmaxf(fminf(pmx[d], tmx[d]) - fmaxf(pmn[d], tmn[d]), 0.f);
                evol  *= fmaxf(fmaxf(pmx[d], tmx[d]) - fminf(pmn[d], tmn[d]), 0.f);
            }
            float uni = vol1 + tvol - inter;
            float giou = inter*frcp(uni) - (evol - uni)*frcp(evol);
            out[(size_t)(r0+r)*NCOL + c] = s - giou;
        }
        return;
    }

    // ================== LAP PATH (blocks 0..15) ==================
    const int b    = blockIdx.x;
    const int lane = tid & 31;
    const int wid  = tid >> 5;
    const float INF = 3.0e38f;
    const float* lbase = &g_lap[(size_t)b*NT*NQ];

    __shared__ ull   vown[NQ];          // packed (v, owner)
    __shared__ float u[NT];
    __shared__ float rmin[NT];
    __shared__ int   ramin[NT];
    __shared__ int   path[NQ];
    __shared__ int   row4col[NQ];
    __shared__ int   col4row[NT];
    __shared__ int   selj[NQ + 2];
    __shared__ float selv[NQ + 2];
    __shared__ int   freelist[NT];
    __shared__ int   qh, nfree_sh;
    volatile ull* vvown = (volatile ull*)vown;

    for (int j = tid; j < NQ; j += TPB) vown[j] = packvo(0.f, -1);
    if (tid < NT) col4row[tid] = -1;
    if (tid == 0) qh = 0;
    __syncthreads();

    // per-row min + argmin (5 warps over 50 rows); u init
    for (int row = wid; row < NT; row += NWARP) {
        const float* rp = lbase + row*NQ;
        float bv = INF; int bi = NQ;
        for (int j = lane; j < NQ; j += 32) {
            float v = rp[j];
            if (v < bv) { bv = v; bi = j; }
        }
        int fi = warp_argmin(bv, bi);
        if (lane == 0) { rmin[row] = bv; ramin[row] = fi; u[row] = bv; }
    }
    __syncthreads();

    // warp 0: greedy conflict-free assignment + freelist
    if (tid < 32) {
        if (lane == 0) {
            #pragma unroll 1
            for (int i = 0; i < NT; i++) {
                int j = ramin[i];
                if (vo_o(vown[j]) == -1) { vown[j] = packvo(0.f, i); col4row[i] = j; }
            }
        }
        __syncwarp();
        int nfree = 0;
        #pragma unroll
        for (int base = 0; base < NT; base += 32) {
            int t = base + lane;
            bool fr = (t < NT) && (col4row[t] == -1);
            unsigned m = __ballot_sync(0xffffffffu, fr);
            int pos = nfree + __popc(m & ((1u << lane) - 1u));
            if (fr) freelist[pos] = t;
            nfree += __popc(m);
        }
        if (lane == 0) nfree_sh = nfree;
    }
    __syncthreads();

    // ---- PARALLEL JV augmenting row reduction: all 5 warps ----
    {
        const int nfree = nfree_sh;
        int budget = SCANBUDGET;
        for (;;) {
            int idx = 0;
            if (lane == 0) idx = atomicAdd(&qh, 1);
            idx = __shfl_sync(0xffffffffu, idx, 0);
            if (idx >= nfree || budget <= 0) break;
            int i = freelist[idx];

            bool alive = true;
            while (alive && budget > 0) {
                budget--;
                const float* lrow = lbase + i*NQ;
                float l1 = INF, l2 = INF; int b1 = NQ; ull p1 = 0;
                #pragma unroll
                for (int k = 0; k < NK; k++) {
                    int j = k*32 + lane;
                    if (j < NQ) {
                        ull pv = vvown[j];
                        float w = lrow[j] - vo_v(pv);
                        if (w < l1) { l2 = l1; l1 = w; b1 = j; p1 = pv; }
                        else if (w < l2) l2 = w;
                    }
                }
                unsigned m1 = __reduce_min_sync(0xffffffffu, fmap(l1));
                unsigned bal = __ballot_sync(0xffffffffu, fmap(l1) == m1);
                int win = __ffs(bal) - 1;
                int j1  = __shfl_sync(0xffffffffu, b1, win);
                ull p64 = __shfl_sync(0xffffffffu, p1, win);
                float u1 = finv(m1);
                float cand = (lane == win) ? l2 : l1;
                float u2 = finv(__reduce_min_sync(0xffffffffu, fmap(cand)));

                int owner1 = vo_o(p64);
                if (!(u1 < u2) && owner1 != -1) { alive = false; break; }

                int ok = 0;
                if (lane == win) {
                    float vnew = vo_v(p64) - (u2 - u1);
                    ok = (atomicCAS(&vown[j1], p64, packvo(vnew, i)) == p64);
                }
                ok = __shfl_sync(0xffffffffu, ok, win);
                if (!ok) continue;

                if (lane == win) {
                    u[i] = u2;
                    col4row[i] = j1;
                    if (owner1 != -1) col4row[owner1] = -1;
                }
                __syncwarp();
                if (owner1 == -1) alive = false;
                else i = owner1;
            }
        }
    }
    __syncthreads();
    if (tid >= 32) return;                 // warp 0 finishes alone

    // extract v / row4col for Dijkstra
    float vloc[NK];
    #pragma unroll
    for (int k = 0; k < NK; k++) {
        int j = k*32 + lane;
        vloc[k] = (j < NQ) ? vo_v(vown[j]) : 0.f;
    }
    for (int j = lane; j < NQ; j += 32) row4col[j] = vo_o(vown[j]);
    __syncwarp();

    float shortest[NK];

    // shortest augmenting path for whatever remains (exact backstop)
    for (int curRow = 0; curRow < NT; curRow++) {
        if (col4row[curRow] != -1) continue;

        #pragma unroll
        for (int k = 0; k < NK; k++) shortest[k] = INF;
        unsigned sc = 0;
        int   i  = curRow;
        float mv = 0.f;
        int   nsteps = 0;
        int   sink = -1;

        while (true) {
            const float base = mv - u[i];
            const float* lrow = lbase + i*NQ;

            float bv = INF; int bi = NQ;
            #pragma unroll
            for (int k = 0; k < NK; k++) {
                int j = k*32 + lane;
                if (j < NQ && !((sc >> k) & 1u)) {
                    float rr = base + lrow[j] - vloc[k];
                    if (rr < shortest[k]) { shortest[k] = rr; path[j] = i; }
                    if (shortest[k] < bv) { bv = shortest[k]; bi = j; }
                }
            }

            int fi = warp_argmin(bv, bi);
            mv = bv;

            if (lane == (fi & 31)) sc |= 1u << (fi >> 5);
            if (lane == 0) { selj[nsteps] = fi; selv[nsteps] = mv; }
            nsteps++;

            int r4 = row4col[fi];
            if (r4 == -1) { sink = fi; break; }
            i = r4;
        }

        __syncwarp();

        if (lane == 0) u[curRow] += mv;
        for (int s = lane; s < nsteps - 1; s += 32) {
            int i2 = row4col[selj[s]];
            u[i2] += mv - selv[s];
        }
        for (int s = 0; s < nsteps; s++) {
            int j = selj[s];
            if ((j & 31) == lane) vloc[j >> 5] -= mv - selv[s];
        }
        __syncwarp();

        if (lane == 0) {
            int j = sink;
            while (true) {
                int i2 = path[j];
                row4col[j] = i2;
                int nj = col4row[i2];
                col4row[i2] = j;
                j = nj;
                if (i2 == curRow) break;
            }
        }
        __syncwarp();
    }

    // emit indices sorted by query (rank counting)
    for (int t = lane; t < NT; t += 32) {
        int q = col4row[t];
        int rank = 0;
        #pragma unroll
        for (int t2 = 0; t2 < NT; t2++) rank += (col4row[t2] < q) ? 1 : 0;
        size_t base = (size_t)NROW * NCOL + (size_t)b * 2 * NT;
        out[base + rank]      = (float)q;
        out[base + NT + rank] = (float)t;
    }
}

// ---------------------------------------------------------
extern "C" void kernel_launch(void* const* d_in, const int* in_sizes, int n_in,
                              void* d_out, int out_size) {
    const float* pred_kp   = (const float*)d_in[0];  // (16,300,51)
    const float* pred_box  = (const float*)d_in[1];  // (16,300,6)
    const float* tgt_box   = (const float*)d_in[2];  // (16,50,6)
    const float* tgt_kp    = (const float*)d_in[3];  // (16,50,51)
    float* out = (float*)d_out;

    diag_kernel<<<DIAG_BLKS, 256>>>(pred_kp, pred_box, tgt_kp, tgt_box);
    fused_kernel<<<BS + GBX*RSLICES, TPB, DYN_BYTES>>>(pred_kp, pred_box, tgt_kp, tgt_box, out);
}